// round 12
// baseline (speedup 1.0000x reference)
#include <cuda_runtime.h>
#include <cuda_fp16.h>
#include <cuda_bf16.h>
#include <math.h>

// ---------------------------------------------------------------------------
// AttentionDisaggregated: prefill (causal self-attn over S=2048) + 1-token decode
// B=2, S=2048, D_MODEL=2048, N_HEADS=16, HEAD_DIM=128
// Round 12: GEMM warp tile 32x64 -> 64x64 (4 warps / 128 threads per CTA):
// smem fragment bytes per HMMA drop 6 -> 4. fp16-native dataflow from R11.
// ---------------------------------------------------------------------------

#define D_MODEL 2048
#define SEQ     2048
#define BATCH   2
#define NHEADS  16
#define HDIM    128
#define MROWS   (BATCH * SEQ)          // 4096
#define PREFILL_ELEMS (BATCH * SEQ * D_MODEL)  // 8388608
#define QSCALE  0.08838834764831843f   // 1/sqrt(128)

// fp16 scratch (device globals -- allocation-free rule)
__device__ __half g_Qh[MROWS * D_MODEL];   // pre-scaled hi
__device__ __half g_Ql[MROWS * D_MODEL];   // pre-scaled lo
__device__ __half g_Kh[MROWS * D_MODEL];
__device__ __half g_Kl[MROWS * D_MODEL];
__device__ __half g_Vth[D_MODEL * MROWS];  // transposed [col][row]
__device__ __half g_Vtl[D_MODEL * MROWS];
__device__ __half g_Ah[MROWS * D_MODEL];   // flash output (fp16)
__device__ __half g_xh[MROWS * D_MODEL];
__device__ __half g_wqt[D_MODEL * D_MODEL];  // [n][k]
__device__ __half g_wkt[D_MODEL * D_MODEL];
__device__ __half g_wvt[D_MODEL * D_MODEL];
__device__ __half g_woh[D_MODEL * D_MODEL];  // [n][k]
// decode fp32 scratch
__device__ float g_q1[BATCH * D_MODEL];
__device__ float g_k1[BATCH * D_MODEL];
__device__ float g_v1[BATCH * D_MODEL];
__device__ float g_a1[BATCH * D_MODEL];

// ---------------------------------------------------------------------------
// helpers
// ---------------------------------------------------------------------------
__device__ __forceinline__ void mma_f16(float* c, const unsigned* a, const unsigned* b) {
    asm volatile(
        "mma.sync.aligned.m16n8k16.row.col.f32.f16.f16.f32 "
        "{%0,%1,%2,%3}, {%4,%5,%6,%7}, {%8,%9}, {%0,%1,%2,%3};\n"
        : "+f"(c[0]), "+f"(c[1]), "+f"(c[2]), "+f"(c[3])
        : "r"(a[0]), "r"(a[1]), "r"(a[2]), "r"(a[3]), "r"(b[0]), "r"(b[1]));
}

__device__ __forceinline__ void split_pair(float x, float y, unsigned& hi, unsigned& lo) {
    __half hx = __float2half_rn(x), hy = __float2half_rn(y);
    __half lx = __float2half_rn(x - __half2float(hx));
    __half ly = __float2half_rn(y - __half2float(hy));
    __half2 h = __halves2half2(hx, hy), l = __halves2half2(lx, ly);
    hi = *reinterpret_cast<unsigned*>(&h);
    lo = *reinterpret_cast<unsigned*>(&l);
}

__device__ __forceinline__ void split1(float v, __half& h, __half& l) {
    h = __float2half_rn(v);
    l = __float2half_rn(v - __half2float(h));
}

// ---------------------------------------------------------------------------
// Conversion kernels (one-time, bandwidth-bound)
// ---------------------------------------------------------------------------
__global__ __launch_bounds__(256) void convert_x_kernel(const float* __restrict__ src)
{
    const int i = (blockIdx.x * 256 + threadIdx.x) * 4;
    float4 v = *reinterpret_cast<const float4*>(src + i);
    __half2 a = __floats2half2_rn(v.x, v.y);
    __half2 b = __floats2half2_rn(v.z, v.w);
    *reinterpret_cast<__half2*>(&g_xh[i]) = a;
    *reinterpret_cast<__half2*>(&g_xh[i + 2]) = b;
}

__global__ __launch_bounds__(256) void convert_wo_kernel(const float* __restrict__ src)
{
    const int i = (blockIdx.x * 256 + threadIdx.x) * 4;
    float4 v = *reinterpret_cast<const float4*>(src + i);
    __half2 a = __floats2half2_rn(v.x, v.y);
    __half2 b = __floats2half2_rn(v.z, v.w);
    *reinterpret_cast<__half2*>(&g_woh[i]) = a;
    *reinterpret_cast<__half2*>(&g_woh[i + 2]) = b;
}

// transpose-convert wq/wk/wv [k][n] fp32 -> [n][k] fp16
__global__ __launch_bounds__(256) void convert_wt_kernel(
    const float* __restrict__ wq, const float* __restrict__ wk, const float* __restrict__ wv)
{
    __shared__ float ts[32][33];
    const int z = blockIdx.z;
    const float* src = (z == 0) ? wq : (z == 1) ? wk : wv;
    __half* dst = (z == 0) ? g_wqt : (z == 1) ? g_wkt : g_wvt;
    const int bx = blockIdx.x * 32;   // n
    const int by = blockIdx.y * 32;   // k
    const int tx = threadIdx.x & 31;
    const int ty = threadIdx.x >> 5;
    #pragma unroll
    for (int i = 0; i < 4; i++)
        ts[ty + 8 * i][tx] = src[(size_t)(by + ty + 8 * i) * 2048 + bx + tx];
    __syncthreads();
    #pragma unroll
    for (int i = 0; i < 4; i++)
        dst[(size_t)(bx + ty + 8 * i) * 2048 + by + tx] = __float2half_rn(ts[tx][ty + 8 * i]);
}

// ---------------------------------------------------------------------------
// Persistent fp16 HMMA GEMM (TT): C[M,N] = A[M,K] @ B[N,K]^T, halves in.
// BM=BN=128, BK=32, 128 threads, 4 warps each 64x64, double-buffered.
// EPI=0: QKV epilogue (z=0 Q split+scale, z=1 K split, z=2 V split transposed)
// EPI=1: fp32 C to Cout.
// ---------------------------------------------------------------------------
#define GSTRIDE 40
#define NPERSIST 296

template <int EPI>
__global__ __launch_bounds__(128) void hgemm_kernel(
    const __half* __restrict__ A,
    const __half* __restrict__ B0, const __half* __restrict__ B1, const __half* __restrict__ B2,
    float* __restrict__ Cout, int ntiles)
{
    __shared__ __half As[2][128][GSTRIDE];
    __shared__ __half Bs[2][128][GSTRIDE];

    const int tid  = threadIdx.x;
    const int lane = tid & 31;
    const int warp = tid >> 5;
    const int wm   = (warp >> 1) * 64;   // warp row origin (64 rows)
    const int wn   = (warp & 1) * 64;    // warp col origin (64 cols)
    const int fr   = lane >> 2;
    const int fc   = lane & 3;

    for (int t = blockIdx.x; t < ntiles; t += NPERSIST) {
        const int z  = (EPI == 0) ? (t >> 9) : 0;
        const int r  = t & 511;
        const int bm = (r >> 4) * 128;
        const int bn = (r & 15) * 128;

        const __half* Bg = (z == 0) ? B0 : (z == 1) ? B1 : B2;

        float acc[4][8][4];
        #pragma unroll
        for (int i = 0; i < 4; i++)
            #pragma unroll
            for (int j = 0; j < 8; j++)
                #pragma unroll
                for (int q = 0; q < 4; q++) acc[i][j][q] = 0.f;

        uint4 ra[4], rb[4];   // one full 64B row each (A row, B row)

        auto issue_loads = [&](int k0) {
            const __half* ap = &A[(size_t)(bm + tid) * 2048 + k0];
            const __half* bp = &Bg[(size_t)(bn + tid) * 2048 + k0];
            #pragma unroll
            for (int j = 0; j < 4; j++) {
                ra[j] = *reinterpret_cast<const uint4*>(ap + 8 * j);
                rb[j] = *reinterpret_cast<const uint4*>(bp + 8 * j);
            }
        };
        auto store_tiles = [&](int sb) {
            #pragma unroll
            for (int j = 0; j < 4; j++) {
                *reinterpret_cast<uint4*>(&As[sb][tid][8 * j]) = ra[j];
                *reinterpret_cast<uint4*>(&Bs[sb][tid][8 * j]) = rb[j];
            }
        };

        issue_loads(0);
        store_tiles(0);
        __syncthreads();

        int buf = 0;
        for (int k0 = 0; k0 < 2048; k0 += 32) {
            const bool has_next = (k0 + 32) < 2048;
            if (has_next) issue_loads(k0 + 32);

            #pragma unroll
            for (int ks = 0; ks < 2; ks++) {
                const int kk = ks * 16 + 2 * fc;
                unsigned afr[4][4];
                #pragma unroll
                for (int mt = 0; mt < 4; mt++) {
                    const int m0 = wm + mt * 16;
                    afr[mt][0] = *reinterpret_cast<const unsigned*>(&As[buf][m0 + fr    ][kk]);
                    afr[mt][1] = *reinterpret_cast<const unsigned*>(&As[buf][m0 + fr + 8][kk]);
                    afr[mt][2] = *reinterpret_cast<const unsigned*>(&As[buf][m0 + fr    ][kk + 8]);
                    afr[mt][3] = *reinterpret_cast<const unsigned*>(&As[buf][m0 + fr + 8][kk + 8]);
                }
                #pragma unroll
                for (int nt = 0; nt < 8; nt++) {
                    const int n0 = wn + nt * 8 + fr;
                    unsigned bfr[2];
                    bfr[0] = *reinterpret_cast<const unsigned*>(&Bs[buf][n0][kk]);
                    bfr[1] = *reinterpret_cast<const unsigned*>(&Bs[buf][n0][kk + 8]);
                    #pragma unroll
                    for (int mt = 0; mt < 4; mt++)
                        mma_f16(acc[mt][nt], afr[mt], bfr);
                }
            }

            if (has_next) store_tiles(buf ^ 1);
            __syncthreads();
            buf ^= 1;
        }

        // ---- epilogue ----
        if (EPI == 1) {
            #pragma unroll
            for (int mt = 0; mt < 4; mt++)
                #pragma unroll
                for (int nt = 0; nt < 8; nt++) {
                    const int row0 = bm + wm + mt * 16 + fr;
                    const int col  = bn + wn + nt * 8 + 2 * fc;
                    *reinterpret_cast<float2*>(&Cout[(size_t)row0 * 2048 + col]) =
                        make_float2(acc[mt][nt][0], acc[mt][nt][1]);
                    *reinterpret_cast<float2*>(&Cout[(size_t)(row0 + 8) * 2048 + col]) =
                        make_float2(acc[mt][nt][2], acc[mt][nt][3]);
                }
        } else if (z < 2) {
            __half* Dh = (z == 0) ? g_Qh : g_Kh;
            __half* Dl = (z == 0) ? g_Ql : g_Kl;
            const float sc = (z == 0) ? QSCALE : 1.f;
            #pragma unroll
            for (int mt = 0; mt < 4; mt++)
                #pragma unroll
                for (int nt = 0; nt < 8; nt++) {
                    const int row0 = bm + wm + mt * 16 + fr;
                    const int col  = bn + wn + nt * 8 + 2 * fc;
                    unsigned h0, l0, h1, l1;
                    split_pair(acc[mt][nt][0] * sc, acc[mt][nt][1] * sc, h0, l0);
                    split_pair(acc[mt][nt][2] * sc, acc[mt][nt][3] * sc, h1, l1);
                    *reinterpret_cast<unsigned*>(&Dh[(size_t)row0 * 2048 + col]) = h0;
                    *reinterpret_cast<unsigned*>(&Dl[(size_t)row0 * 2048 + col]) = l0;
                    *reinterpret_cast<unsigned*>(&Dh[(size_t)(row0 + 8) * 2048 + col]) = h1;
                    *reinterpret_cast<unsigned*>(&Dl[(size_t)(row0 + 8) * 2048 + col]) = l1;
                }
        } else {
            // V: transposed split write  g_Vt*[col][row]
            #pragma unroll
            for (int mt = 0; mt < 4; mt++)
                #pragma unroll
                for (int nt = 0; nt < 8; nt++) {
                    const int row0 = bm + wm + mt * 16 + fr;
                    const int col  = bn + wn + nt * 8 + 2 * fc;
                    #pragma unroll
                    for (int q = 0; q < 4; q++) {
                        const int rr = row0 + (q >> 1) * 8;
                        const int cc = col + (q & 1);
                        __half h, l;
                        split1(acc[mt][nt][q], h, l);
                        g_Vth[(size_t)cc * MROWS + rr] = h;
                        g_Vtl[(size_t)cc * MROWS + rr] = l;
                    }
                }
        }
        if (EPI == 0) __syncthreads();   // protect smem reuse across persistent iters
    }
}

// ---------------------------------------------------------------------------
// Flash attention prefill, fp16 hi/lo 3-mma split, register softmax.
// All operands pre-split/pre-transposed in gmem: tile loads are pure copies.
// BQ=BK=64, 256 threads; warp pair shares 16 Q rows, splits 64 tokens.
// ---------------------------------------------------------------------------
#define FQS 136   // Q/K row stride (halves)
#define FVS 72    // Vt row stride (halves)

#define OFF_QH  0
#define OFF_QL  (OFF_QH + 64 * FQS * 2)
#define OFF_KH  (OFF_QL + 64 * FQS * 2)
#define OFF_KL  (OFF_KH + 64 * FQS * 2)
#define OFF_VTH (OFF_KL + 64 * FQS * 2)
#define OFF_VTL (OFF_VTH + 128 * FVS * 2)
#define OFF_PM  (OFF_VTL + 128 * FVS * 2)
#define OFF_PSUM (OFF_PM + 128 * 4)
#define OFF_M   (OFF_PSUM + 128 * 4)
#define OFF_L   (OFF_M + 64 * 4)
#define FLASH_SMEM_BYTES (OFF_L + 64 * 4)

__global__ __launch_bounds__(256) void flash_hmma_kernel()
{
    extern __shared__ char fsm[];
    __half* Qhs = reinterpret_cast<__half*>(fsm + OFF_QH);
    __half* Qls = reinterpret_cast<__half*>(fsm + OFF_QL);
    __half* Khs = reinterpret_cast<__half*>(fsm + OFF_KH);
    __half* Kls = reinterpret_cast<__half*>(fsm + OFF_KL);
    __half* Vhs = reinterpret_cast<__half*>(fsm + OFF_VTH);
    __half* Vls = reinterpret_cast<__half*>(fsm + OFF_VTL);
    float*  pm   = reinterpret_cast<float*>(fsm + OFF_PM);
    float*  psum = reinterpret_cast<float*>(fsm + OFF_PSUM);
    float*  m_s  = reinterpret_cast<float*>(fsm + OFF_M);
    float*  l_s  = reinterpret_cast<float*>(fsm + OFF_L);

    const int qi = blockIdx.x;
    const int n  = blockIdx.y;
    const int b  = blockIdx.z;
    const int tid  = threadIdx.x;
    const int lane = tid & 31;
    const int warp = tid >> 5;
    const int wm   = (warp >> 1) * 16;
    const int wh   = (warp & 1);
    const int fr   = lane >> 2;
    const int fc   = lane & 3;

    const int qk_r = tid >> 2;
    const int qk_c = (tid & 3) * 32;
    const int v_r = tid >> 1;
    const int v_c = (tid & 1) * 32;

    const size_t hcol = (size_t)n * HDIM;
    const int r0 = wm + fr, r1 = wm + fr + 8;

    // ---- load Q tile (pure copy; already scaled+split) ----
    {
        const size_t base = (size_t)(b * SEQ + qi * 64 + qk_r) * 2048 + hcol + qk_c;
        #pragma unroll
        for (int i = 0; i < 4; i++) {
            *reinterpret_cast<uint4*>(&Qhs[qk_r * FQS + qk_c + 8 * i]) =
                *reinterpret_cast<const uint4*>(&g_Qh[base + 8 * i]);
            *reinterpret_cast<uint4*>(&Qls[qk_r * FQS + qk_c + 8 * i]) =
                *reinterpret_cast<const uint4*>(&g_Ql[base + 8 * i]);
        }
    }
    if (tid < 64) { m_s[tid] = -INFINITY; l_s[tid] = 0.f; }

    // ---- K tile 0 -> smem; V tile 0 -> regs ----
    {
        const size_t base = (size_t)(b * SEQ + qk_r) * 2048 + hcol + qk_c;
        #pragma unroll
        for (int i = 0; i < 4; i++) {
            *reinterpret_cast<uint4*>(&Khs[qk_r * FQS + qk_c + 8 * i]) =
                *reinterpret_cast<const uint4*>(&g_Kh[base + 8 * i]);
            *reinterpret_cast<uint4*>(&Kls[qk_r * FQS + qk_c + 8 * i]) =
                *reinterpret_cast<const uint4*>(&g_Kl[base + 8 * i]);
        }
    }
    uint4 vrh[4], vrl[4];
    {
        const size_t base = (hcol + v_r) * (size_t)MROWS + b * SEQ + v_c;
        #pragma unroll
        for (int i = 0; i < 4; i++) {
            vrh[i] = *reinterpret_cast<const uint4*>(&g_Vth[base + 8 * i]);
            vrl[i] = *reinterpret_cast<const uint4*>(&g_Vtl[base + 8 * i]);
        }
    }
    __syncthreads();

    float o[16][4];
    #pragma unroll
    for (int i = 0; i < 16; i++)
        #pragma unroll
        for (int j = 0; j < 4; j++) o[i][j] = 0.f;

    for (int kt = 0; kt <= qi; kt++) {
        // ---- 1. S = Q K^T over own 32 cols (fp16 3-mma split) ----
        float sacc[4][4];
        #pragma unroll
        for (int i = 0; i < 4; i++)
            #pragma unroll
            for (int j = 0; j < 4; j++) sacc[i][j] = 0.f;

        #pragma unroll
        for (int kc = 0; kc < 8; kc++) {
            const int kb = kc * 16 + 2 * fc;
            const int ar0 = r0 * FQS + kb;
            const int ar1 = r1 * FQS + kb;
            unsigned ah[4], al[4];
            ah[0] = *reinterpret_cast<const unsigned*>(&Qhs[ar0]);
            ah[1] = *reinterpret_cast<const unsigned*>(&Qhs[ar1]);
            ah[2] = *reinterpret_cast<const unsigned*>(&Qhs[ar0 + 8]);
            ah[3] = *reinterpret_cast<const unsigned*>(&Qhs[ar1 + 8]);
            al[0] = *reinterpret_cast<const unsigned*>(&Qls[ar0]);
            al[1] = *reinterpret_cast<const unsigned*>(&Qls[ar1]);
            al[2] = *reinterpret_cast<const unsigned*>(&Qls[ar0 + 8]);
            al[3] = *reinterpret_cast<const unsigned*>(&Qls[ar1 + 8]);
            #pragma unroll
            for (int nt = 0; nt < 4; nt++) {
                const int br = (wh * 32 + nt * 8 + fr) * FQS + kb;
                unsigned bh[2], bl[2];
                bh[0] = *reinterpret_cast<const unsigned*>(&Khs[br]);
                bh[1] = *reinterpret_cast<const unsigned*>(&Khs[br + 8]);
                bl[0] = *reinterpret_cast<const unsigned*>(&Kls[br]);
                bl[1] = *reinterpret_cast<const unsigned*>(&Kls[br + 8]);
                mma_f16(sacc[nt], ah, bh);
                mma_f16(sacc[nt], ah, bl);
                mma_f16(sacc[nt], al, bh);
            }
        }

        // ---- mask + local row max + quad reduce ----
        if (kt == qi) {
            #pragma unroll
            for (int nt = 0; nt < 4; nt++) {
                const int ct = wh * 32 + nt * 8 + 2 * fc;
                if (ct     > r0) sacc[nt][0] = -INFINITY;
                if (ct + 1 > r0) sacc[nt][1] = -INFINITY;
                if (ct     > r1) sacc[nt][2] = -INFINITY;
                if (ct + 1 > r1) sacc[nt][3] = -INFINITY;
            }
        }
        float mx0 = -INFINITY, mx1 = -INFINITY;
        #pragma unroll
        for (int nt = 0; nt < 4; nt++) {
            mx0 = fmaxf(mx0, fmaxf(sacc[nt][0], sacc[nt][1]));
            mx1 = fmaxf(mx1, fmaxf(sacc[nt][2], sacc[nt][3]));
        }
        mx0 = fmaxf(mx0, __shfl_xor_sync(0xffffffffu, mx0, 1));
        mx0 = fmaxf(mx0, __shfl_xor_sync(0xffffffffu, mx0, 2));
        mx1 = fmaxf(mx1, __shfl_xor_sync(0xffffffffu, mx1, 1));
        mx1 = fmaxf(mx1, __shfl_xor_sync(0xffffffffu, mx1, 2));
        __syncthreads();   // prev PV done with Vt; Kh/Kl consumed

        // ---- 2. V regs -> Vt smem; pm write; prefetch next K ----
        #pragma unroll
        for (int i = 0; i < 4; i++) {
            *reinterpret_cast<uint4*>(&Vhs[v_r * FVS + v_c + 8 * i]) = vrh[i];
            *reinterpret_cast<uint4*>(&Vls[v_r * FVS + v_c + 8 * i]) = vrl[i];
        }
        if (fc == 0) { pm[wh * 64 + r0] = mx0; pm[wh * 64 + r1] = mx1; }
        uint4 krh[4], krl[4];
        if (kt < qi) {
            const size_t base = (size_t)(b * SEQ + (kt + 1) * 64 + qk_r) * 2048 + hcol + qk_c;
            #pragma unroll
            for (int i = 0; i < 4; i++) {
                krh[i] = *reinterpret_cast<const uint4*>(&g_Kh[base + 8 * i]);
                krl[i] = *reinterpret_cast<const uint4*>(&g_Kl[base + 8 * i]);
            }
        }
        __syncthreads();   // Vt, pm visible

        // ---- 3. softmax in regs; pack P fragments; partial sums ----
        const float mold0 = m_s[r0], mold1 = m_s[r1];
        const float mn0 = fmaxf(mold0, fmaxf(pm[r0], pm[64 + r0]));
        const float mn1 = fmaxf(mold1, fmaxf(pm[r1], pm[64 + r1]));
        const float alpha0 = __expf(mold0 - mn0);
        const float alpha1 = __expf(mold1 - mn1);

        unsigned Pfh[2][4], Pfl[2][4];
        float s0 = 0.f, s1 = 0.f;
        #pragma unroll
        for (int j = 0; j < 2; j++) {
            float e00 = __expf(sacc[2*j][0] - mn0),   e01 = __expf(sacc[2*j][1] - mn0);
            float e02 = __expf(sacc[2*j][2] - mn1),   e03 = __expf(sacc[2*j][3] - mn1);
            float e10 = __expf(sacc[2*j+1][0] - mn0), e11 = __expf(sacc[2*j+1][1] - mn0);
            float e12 = __expf(sacc[2*j+1][2] - mn1), e13 = __expf(sacc[2*j+1][3] - mn1);
            s0 += e00 + e01 + e10 + e11;
            s1 += e02 + e03 + e12 + e13;
            split_pair(e00, e01, Pfh[j][0], Pfl[j][0]);
            split_pair(e02, e03, Pfh[j][1], Pfl[j][1]);
            split_pair(e10, e11, Pfh[j][2], Pfl[j][2]);
            split_pair(e12, e13, Pfh[j][3], Pfl[j][3]);
        }
        s0 += __shfl_xor_sync(0xffffffffu, s0, 1);
        s0 += __shfl_xor_sync(0xffffffffu, s0, 2);
        s1 += __shfl_xor_sync(0xffffffffu, s1, 1);
        s1 += __shfl_xor_sync(0xffffffffu, s1, 2);
        if (fc == 0) { psum[wh * 64 + r0] = s0; psum[wh * 64 + r1] = s1; }
        __syncthreads();   // psum visible

        // ---- 4. l/m update; O*=alpha; PV; K regs -> smem; V prefetch ----
        if (wh == 0 && fc == 0) {
            l_s[r0] = l_s[r0] * alpha0 + psum[r0] + psum[64 + r0];
            l_s[r1] = l_s[r1] * alpha1 + psum[r1] + psum[64 + r1];
            m_s[r0] = mn0;
            m_s[r1] = mn1;
        }
        #pragma unroll
        for (int nt = 0; nt < 16; nt++) {
            o[nt][0] *= alpha0; o[nt][1] *= alpha0;
            o[nt][2] *= alpha1; o[nt][3] *= alpha1;
        }
        if (kt < qi) {
            #pragma unroll
            for (int i = 0; i < 4; i++) {
                *reinterpret_cast<uint4*>(&Khs[qk_r * FQS + qk_c + 8 * i]) = krh[i];
                *reinterpret_cast<uint4*>(&Kls[qk_r * FQS + qk_c + 8 * i]) = krl[i];
            }
            const size_t base = (hcol + v_r) * (size_t)MROWS + b * SEQ + (kt + 1) * 64 + v_c;
            #pragma unroll
            for (int i = 0; i < 4; i++) {
                vrh[i] = *reinterpret_cast<const uint4*>(&g_Vth[base + 8 * i]);
                vrl[i] = *reinterpret_cast<const uint4*>(&g_Vtl[base + 8 * i]);
            }
        }
        #pragma unroll
        for (int j = 0; j < 2; j++) {
            const int w = wh * 2 + j;       // 16-token window
            #pragma unroll
            for (int nt = 0; nt < 16; nt++) {
                const int br = (nt * 8 + fr) * FVS + w * 16 + 2 * fc;
                unsigned bh[2], bl[2];
                bh[0] = *reinterpret_cast<const unsigned*>(&Vhs[br]);
                bh[1] = *reinterpret_cast<const unsigned*>(&Vhs[br + 8]);
                bl[0] = *reinterpret_cast<const unsigned*>(&Vls[br]);
                bl[1] = *reinterpret_cast<const unsigned*>(&Vls[br + 8]);
                mma_f16(o[nt], Pfh[j], bh);
                mma_f16(o[nt], Pfh[j], bl);
                mma_f16(o[nt], Pfl[j], bh);
            }
        }
        __syncthreads();   // K store visible; Vt consumed
    }

    // ---- epilogue: merge partial O across warp pairs, write fp16 A ----
    float* Omrg = reinterpret_cast<float*>(fsm + OFF_KH);   // 32KB scratch
    if (wh == 1) {
        float* dst = &Omrg[((warp >> 1) * 32 + lane) * 64];
        #pragma unroll
        for (int nt = 0; nt < 16; nt++) {
            float4 v = make_float4(o[nt][0], o[nt][1], o[nt][2], o[nt][3]);
            *reinterpret_cast<float4*>(dst + nt * 4) = v;
        }
    }
    __syncthreads();
    if (wh == 0) {
        const float inv0 = 1.f / l_s[r0];
        const float inv1 = 1.f / l_s[r1];
        const float* src = &Omrg[((warp >> 1) * 32 + lane) * 64];
        __half* Ab = g_Ah + (size_t)(b * SEQ + qi * 64) * 2048 + hcol;
        #pragma unroll
        for (int nt = 0; nt < 16; nt++) {
            float4 v = *reinterpret_cast<const float4*>(src + nt * 4);
            const int col = nt * 8 + 2 * fc;
            __half2 p0 = __floats2half2_rn((o[nt][0] + v.x) * inv0, (o[nt][1] + v.y) * inv0);
            __half2 p1 = __floats2half2_rn((o[nt][2] + v.z) * inv1, (o[nt][3] + v.w) * inv1);
            *reinterpret_cast<__half2*>(&Ab[(size_t)r0 * 2048 + col]) = p0;
            *reinterpret_cast<__half2*>(&Ab[(size_t)r1 * 2048 + col]) = p1;
        }
    }
}

// ---------------------------------------------------------------------------
// Decode kernels
// ---------------------------------------------------------------------------
__global__ void decode_init_kernel()
{
    const int i = blockIdx.x * 256 + threadIdx.x;
    if (i < BATCH * D_MODEL) {
        g_q1[i] = 0.f; g_k1[i] = 0.f; g_v1[i] = 0.f;
    }
}

__global__ __launch_bounds__(256) void decode_proj_kernel(
    const float* __restrict__ xnew,
    const float* __restrict__ wq, const float* __restrict__ wk,
    const float* __restrict__ wv)
{
    const int col = blockIdx.x * 256 + threadIdx.x;
    const int b = blockIdx.y & 1;
    const int w = blockIdx.y >> 1;
    const int d0 = blockIdx.z * 256;
    const float* wsel = (w == 0) ? wq : (w == 1) ? wk : wv;
    float* osel = (w == 0) ? g_q1 : (w == 1) ? g_k1 : g_v1;

    __shared__ float xs[256];
    xs[threadIdx.x] = xnew[b * D_MODEL + d0 + threadIdx.x];
    __syncthreads();

    float acc = 0.f;
    #pragma unroll 8
    for (int d = 0; d < 256; d++)
        acc += xs[d] * wsel[(size_t)(d0 + d) * D_MODEL + col];
    atomicAdd(&osel[b * D_MODEL + col], acc);
}

__global__ __launch_bounds__(256) void decode_attn_kernel()
{
    const int n = blockIdx.x;
    const int b = blockIdx.y;
    const int tid = threadIdx.x;
    const int lane = tid & 31;
    const int warp = tid >> 5;

    __shared__ float qs[HDIM];
    __shared__ float sc[SEQ + 1];
    __shared__ float red[256];

    if (tid < HDIM) qs[tid] = g_q1[b * D_MODEL + n * HDIM + tid];
    __syncthreads();

    const float scale = QSCALE;
    const float4 qv = *reinterpret_cast<const float4*>(&qs[lane * 4]);

    for (int t = warp; t < SEQ + 1; t += 8) {
        float s;
        if (t < SEQ) {
            const size_t base = (size_t)(b * SEQ + t) * 2048 + n * HDIM + lane * 4;
            float k0 = __half2float(g_Kh[base + 0]) + __half2float(g_Kl[base + 0]);
            float k1 = __half2float(g_Kh[base + 1]) + __half2float(g_Kl[base + 1]);
            float k2 = __half2float(g_Kh[base + 2]) + __half2float(g_Kl[base + 2]);
            float k3 = __half2float(g_Kh[base + 3]) + __half2float(g_Kl[base + 3]);
            s = qv.x * k0 + qv.y * k1 + qv.z * k2 + qv.w * k3;
        } else {
            const float* kr = g_k1 + b * D_MODEL + n * HDIM;
            float4 kv = *reinterpret_cast<const float4*>(&kr[lane * 4]);
            s = qv.x * kv.x + qv.y * kv.y + qv.z * kv.z + qv.w * kv.w;
        }
        #pragma unroll
        for (int o = 16; o > 0; o >>= 1) s += __shfl_xor_sync(0xffffffffu, s, o);
        if (lane == 0) sc[t] = s * scale;
    }
    __syncthreads();

    float mx = -INFINITY;
    for (int t = tid; t < SEQ + 1; t += 256) mx = fmaxf(mx, sc[t]);
    red[tid] = mx;
    __syncthreads();
    for (int s = 128; s > 0; s >>= 1) {
        if (tid < s) red[tid] = fmaxf(red[tid], red[tid + s]);
        __syncthreads();
    }
    mx = red[0];
    __syncthreads();

    float sum = 0.f;
    for (int t = tid; t < SEQ + 1; t += 256) {
        float p = __expf(sc[t] - mx);
        sc[t] = p;
        sum += p;
    }
    red[tid] = sum;
    __syncthreads();
    for (int s = 128; s > 0; s >>= 1) {
        if (tid < s) red[tid] += red[tid + s];
        __syncthreads();
    }
    const float inv = 1.f / red[0];
    __syncthreads();

    // V accumulation: Vt columns are contiguous in t per (n,h)
    const int h = tid & 127;
    const int half_ = tid >> 7;
    const __half* vth = &g_Vth[(size_t)(n * HDIM + h) * MROWS + b * SEQ];
    const __half* vtl = &g_Vtl[(size_t)(n * HDIM + h) * MROWS + b * SEQ];
    float acc = 0.f;
    #pragma unroll 4
    for (int t = half_; t < SEQ; t += 2)
        acc += sc[t] * (__half2float(vth[t]) + __half2float(vtl[t]));
    if (half_ == 0) acc += sc[SEQ] * g_v1[b * D_MODEL + n * HDIM + h];
    red[tid] = acc;
    __syncthreads();
    if (tid < 128)
        g_a1[b * D_MODEL + n * HDIM + tid] = (red[tid] + red[tid + 128]) * inv;
}

__global__ __launch_bounds__(256) void decode_out_kernel(
    const float* __restrict__ wo, float* __restrict__ out)
{
    const int gw = (blockIdx.x * 256 + threadIdx.x) >> 5;
    const int lane = threadIdx.x & 31;
    if (gw >= BATCH * D_MODEL) return;
    const int b = gw >> 11;
    const int d = gw & (D_MODEL - 1);

    const float* a = g_a1 + b * D_MODEL;
    const float* w = wo + (size_t)d * D_MODEL;
    float acc = 0.f;
    for (int k = lane * 4; k < D_MODEL; k += 128) {
        float4 av = *reinterpret_cast<const float4*>(a + k);
        float4 wv = *reinterpret_cast<const float4*>(w + k);
        acc += av.x * wv.x + av.y * wv.y + av.z * wv.z + av.w * wv.w;
    }
    #pragma unroll
    for (int o = 16; o > 0; o >>= 1) acc += __shfl_down_sync(0xffffffff, acc, o);
    if (lane == 0) out[PREFILL_ELEMS + b * D_MODEL + d] = acc;
}

// ---------------------------------------------------------------------------
extern "C" void kernel_launch(void* const* d_in, const int* in_sizes, int n_in,
                              void* d_out, int out_size)
{
    const float* x     = (const float*)d_in[0];
    const float* x_new = (const float*)d_in[1];
    const float* wq    = (const float*)d_in[2];
    const float* wk    = (const float*)d_in[3];
    const float* wv    = (const float*)d_in[4];
    const float* wo    = (const float*)d_in[5];
    float* out = (float*)d_out;

    __half *pxh, *pAh, *pwqt, *pwkt, *pwvt, *pwoh;
    cudaGetSymbolAddress((void**)&pxh,  g_xh);
    cudaGetSymbolAddress((void**)&pAh,  g_Ah);
    cudaGetSymbolAddress((void**)&pwqt, g_wqt);
    cudaGetSymbolAddress((void**)&pwkt, g_wkt);
    cudaGetSymbolAddress((void**)&pwvt, g_wvt);
    cudaGetSymbolAddress((void**)&pwoh, g_woh);

    cudaFuncSetAttribute(flash_hmma_kernel,
                         cudaFuncAttributeMaxDynamicSharedMemorySize, FLASH_SMEM_BYTES);

    // 0. one-time conversions
    convert_x_kernel<<<PREFILL_ELEMS / 4 / 256, 256>>>(x);
    convert_wo_kernel<<<(D_MODEL * D_MODEL) / 4 / 256, 256>>>(wo);
    dim3 wtg(64, 64, 3);
    convert_wt_kernel<<<wtg, 256>>>(wq, wk, wv);

    // 1. Fused Q/K/V projections (fp16-native, 64x64 warp tiles)
    hgemm_kernel<0><<<NPERSIST, 128>>>(pxh, pwqt, pwkt, pwvt, nullptr, 1536);

    // 2-3. decode init + projections
    decode_init_kernel<<<(BATCH * D_MODEL + 255) / 256, 256>>>();
    dim3 dpgrid(D_MODEL / 256, BATCH * 3, 8);
    decode_proj_kernel<<<dpgrid, 256>>>(x_new, wq, wk, wv);

    // 4. Prefill flash attention  <-- profiled slot
    dim3 fgrid(SEQ / 64, NHEADS, BATCH);
    flash_hmma_kernel<<<fgrid, 256, FLASH_SMEM_BYTES>>>();

    // 5. Output projection (fp16-native, 64x64 warp tiles)
    hgemm_kernel<1><<<NPERSIST, 128>>>(pAh, pwoh, pwoh, pwoh, out, 512);

    // 6-7. decode attention + output projection
    dim3 dagrid(NHEADS, BATCH);
    decode_attn_kernel<<<dagrid, 256>>>();
    decode_out_kernel<<<512, 256>>>(wo, out);
}

// round 13
// speedup vs baseline: 1.2271x; 1.2271x over previous
#include <cuda_runtime.h>
#include <cuda_fp16.h>
#include <cuda_bf16.h>
#include <math.h>

// ---------------------------------------------------------------------------
// AttentionDisaggregated: prefill (causal self-attn over S=2048) + 1-token decode
// B=2, S=2048, D_MODEL=2048, N_HEADS=16, HEAD_DIM=128
// Round 13: GEMM reverted to R11 (256 thr, 32x64 warp tiles, 16 warps/SM).
// Flash: 3 syncs/tile, m/l in registers, own-half exp + corr at pack.
// decode_attn fully vectorized (uint2 K dot, uint4 V streams).
// ---------------------------------------------------------------------------

#define D_MODEL 2048
#define SEQ     2048
#define BATCH   2
#define NHEADS  16
#define HDIM    128
#define MROWS   (BATCH * SEQ)          // 4096
#define PREFILL_ELEMS (BATCH * SEQ * D_MODEL)  // 8388608
#define QSCALE  0.08838834764831843f   // 1/sqrt(128)

// fp16 scratch (device globals -- allocation-free rule)
__device__ __half g_Qh[MROWS * D_MODEL];   // pre-scaled hi
__device__ __half g_Ql[MROWS * D_MODEL];   // pre-scaled lo
__device__ __half g_Kh[MROWS * D_MODEL];
__device__ __half g_Kl[MROWS * D_MODEL];
__device__ __half g_Vth[D_MODEL * MROWS];  // transposed [col][row]
__device__ __half g_Vtl[D_MODEL * MROWS];
__device__ __half g_Ah[MROWS * D_MODEL];   // flash output (fp16)
__device__ __half g_xh[MROWS * D_MODEL];
__device__ __half g_wqt[D_MODEL * D_MODEL];  // [n][k]
__device__ __half g_wkt[D_MODEL * D_MODEL];
__device__ __half g_wvt[D_MODEL * D_MODEL];
__device__ __half g_woh[D_MODEL * D_MODEL];  // [n][k]
// decode fp32 scratch
__device__ float g_q1[BATCH * D_MODEL];
__device__ float g_k1[BATCH * D_MODEL];
__device__ float g_v1[BATCH * D_MODEL];
__device__ float g_a1[BATCH * D_MODEL];

// ---------------------------------------------------------------------------
// helpers
// ---------------------------------------------------------------------------
__device__ __forceinline__ void mma_f16(float* c, const unsigned* a, const unsigned* b) {
    asm volatile(
        "mma.sync.aligned.m16n8k16.row.col.f32.f16.f16.f32 "
        "{%0,%1,%2,%3}, {%4,%5,%6,%7}, {%8,%9}, {%0,%1,%2,%3};\n"
        : "+f"(c[0]), "+f"(c[1]), "+f"(c[2]), "+f"(c[3])
        : "r"(a[0]), "r"(a[1]), "r"(a[2]), "r"(a[3]), "r"(b[0]), "r"(b[1]));
}

__device__ __forceinline__ void split_pair(float x, float y, unsigned& hi, unsigned& lo) {
    __half hx = __float2half_rn(x), hy = __float2half_rn(y);
    __half lx = __float2half_rn(x - __half2float(hx));
    __half ly = __float2half_rn(y - __half2float(hy));
    __half2 h = __halves2half2(hx, hy), l = __halves2half2(lx, ly);
    hi = *reinterpret_cast<unsigned*>(&h);
    lo = *reinterpret_cast<unsigned*>(&l);
}

__device__ __forceinline__ void split1(float v, __half& h, __half& l) {
    h = __float2half_rn(v);
    l = __float2half_rn(v - __half2float(h));
}

// ---------------------------------------------------------------------------
// Conversion kernels (one-time, bandwidth-bound)
// ---------------------------------------------------------------------------
__global__ __launch_bounds__(256) void convert_x_kernel(const float* __restrict__ src)
{
    const int i = (blockIdx.x * 256 + threadIdx.x) * 4;
    float4 v = *reinterpret_cast<const float4*>(src + i);
    __half2 a = __floats2half2_rn(v.x, v.y);
    __half2 b = __floats2half2_rn(v.z, v.w);
    *reinterpret_cast<__half2*>(&g_xh[i]) = a;
    *reinterpret_cast<__half2*>(&g_xh[i + 2]) = b;
}

__global__ __launch_bounds__(256) void convert_wo_kernel(const float* __restrict__ src)
{
    const int i = (blockIdx.x * 256 + threadIdx.x) * 4;
    float4 v = *reinterpret_cast<const float4*>(src + i);
    __half2 a = __floats2half2_rn(v.x, v.y);
    __half2 b = __floats2half2_rn(v.z, v.w);
    *reinterpret_cast<__half2*>(&g_woh[i]) = a;
    *reinterpret_cast<__half2*>(&g_woh[i + 2]) = b;
}

// transpose-convert wq/wk/wv [k][n] fp32 -> [n][k] fp16
__global__ __launch_bounds__(256) void convert_wt_kernel(
    const float* __restrict__ wq, const float* __restrict__ wk, const float* __restrict__ wv)
{
    __shared__ float ts[32][33];
    const int z = blockIdx.z;
    const float* src = (z == 0) ? wq : (z == 1) ? wk : wv;
    __half* dst = (z == 0) ? g_wqt : (z == 1) ? g_wkt : g_wvt;
    const int bx = blockIdx.x * 32;   // n
    const int by = blockIdx.y * 32;   // k
    const int tx = threadIdx.x & 31;
    const int ty = threadIdx.x >> 5;
    #pragma unroll
    for (int i = 0; i < 4; i++)
        ts[ty + 8 * i][tx] = src[(size_t)(by + ty + 8 * i) * 2048 + bx + tx];
    __syncthreads();
    #pragma unroll
    for (int i = 0; i < 4; i++)
        dst[(size_t)(bx + ty + 8 * i) * 2048 + by + tx] = __float2half_rn(ts[tx][ty + 8 * i]);
}

// ---------------------------------------------------------------------------
// Persistent fp16 HMMA GEMM (TT): C[M,N] = A[M,K] @ B[N,K]^T, halves in.
// BM=BN=128, BK=32, 256 threads, 8 warps each 32x64, double-buffered. (R11)
// EPI=0: QKV epilogue (z=0 Q split+scale, z=1 K split, z=2 V split transposed)
// EPI=1: fp32 C to Cout.
// ---------------------------------------------------------------------------
#define GSTRIDE 40
#define NPERSIST 296

template <int EPI>
__global__ __launch_bounds__(256, 2) void hgemm_kernel(
    const __half* __restrict__ A,
    const __half* __restrict__ B0, const __half* __restrict__ B1, const __half* __restrict__ B2,
    float* __restrict__ Cout, int ntiles)
{
    __shared__ __half As[2][128][GSTRIDE];
    __shared__ __half Bs[2][128][GSTRIDE];

    const int tid  = threadIdx.x;
    const int lane = tid & 31;
    const int warp = tid >> 5;
    const int wm   = (warp >> 1) * 32;
    const int wn   = (warp & 1) * 64;
    const int fr   = lane >> 2;
    const int fc   = lane & 3;

    const int l_r = tid >> 1;
    const int l_k = (tid & 1) * 16;

    for (int t = blockIdx.x; t < ntiles; t += NPERSIST) {
        const int z  = (EPI == 0) ? (t >> 9) : 0;
        const int r  = t & 511;
        const int bm = (r >> 4) * 128;
        const int bn = (r & 15) * 128;

        const __half* Bg = (z == 0) ? B0 : (z == 1) ? B1 : B2;

        float acc[2][8][4];
        #pragma unroll
        for (int i = 0; i < 2; i++)
            #pragma unroll
            for (int j = 0; j < 8; j++)
                #pragma unroll
                for (int q = 0; q < 4; q++) acc[i][j][q] = 0.f;

        uint4 ra[2], rb[2];

        auto issue_loads = [&](int k0) {
            #pragma unroll
            for (int j = 0; j < 2; j++) {
                ra[j] = *reinterpret_cast<const uint4*>(&A[(size_t)(bm + l_r) * 2048 + k0 + l_k + 8 * j]);
                rb[j] = *reinterpret_cast<const uint4*>(&Bg[(size_t)(bn + l_r) * 2048 + k0 + l_k + 8 * j]);
            }
        };
        auto store_tiles = [&](int sb) {
            #pragma unroll
            for (int j = 0; j < 2; j++) {
                *reinterpret_cast<uint4*>(&As[sb][l_r][l_k + 8 * j]) = ra[j];
                *reinterpret_cast<uint4*>(&Bs[sb][l_r][l_k + 8 * j]) = rb[j];
            }
        };

        issue_loads(0);
        store_tiles(0);
        __syncthreads();

        int buf = 0;
        for (int k0 = 0; k0 < 2048; k0 += 32) {
            const bool has_next = (k0 + 32) < 2048;
            if (has_next) issue_loads(k0 + 32);

            #pragma unroll
            for (int ks = 0; ks < 2; ks++) {
                const int kk = ks * 16 + 2 * fc;
                unsigned afr[2][4];
                #pragma unroll
                for (int mt = 0; mt < 2; mt++) {
                    const int m0 = wm + mt * 16;
                    afr[mt][0] = *reinterpret_cast<const unsigned*>(&As[buf][m0 + fr    ][kk]);
                    afr[mt][1] = *reinterpret_cast<const unsigned*>(&As[buf][m0 + fr + 8][kk]);
                    afr[mt][2] = *reinterpret_cast<const unsigned*>(&As[buf][m0 + fr    ][kk + 8]);
                    afr[mt][3] = *reinterpret_cast<const unsigned*>(&As[buf][m0 + fr + 8][kk + 8]);
                }
                #pragma unroll
                for (int nt = 0; nt < 8; nt++) {
                    const int n0 = wn + nt * 8 + fr;
                    unsigned bfr[2];
                    bfr[0] = *reinterpret_cast<const unsigned*>(&Bs[buf][n0][kk]);
                    bfr[1] = *reinterpret_cast<const unsigned*>(&Bs[buf][n0][kk + 8]);
                    mma_f16(acc[0][nt], afr[0], bfr);
                    mma_f16(acc[1][nt], afr[1], bfr);
                }
            }

            if (has_next) store_tiles(buf ^ 1);
            __syncthreads();
            buf ^= 1;
        }

        // ---- epilogue ----
        if (EPI == 1) {
            #pragma unroll
            for (int mt = 0; mt < 2; mt++)
                #pragma unroll
                for (int nt = 0; nt < 8; nt++) {
                    const int row0 = bm + wm + mt * 16 + fr;
                    const int col  = bn + wn + nt * 8 + 2 * fc;
                    *reinterpret_cast<float2*>(&Cout[(size_t)row0 * 2048 + col]) =
                        make_float2(acc[mt][nt][0], acc[mt][nt][1]);
                    *reinterpret_cast<float2*>(&Cout[(size_t)(row0 + 8) * 2048 + col]) =
                        make_float2(acc[mt][nt][2], acc[mt][nt][3]);
                }
        } else if (z < 2) {
            __half* Dh = (z == 0) ? g_Qh : g_Kh;
            __half* Dl = (z == 0) ? g_Ql : g_Kl;
            const float sc = (z == 0) ? QSCALE : 1.f;
            #pragma unroll
            for (int mt = 0; mt < 2; mt++)
                #pragma unroll
                for (int nt = 0; nt < 8; nt++) {
                    const int row0 = bm + wm + mt * 16 + fr;
                    const int col  = bn + wn + nt * 8 + 2 * fc;
                    unsigned h0, l0, h1, l1;
                    split_pair(acc[mt][nt][0] * sc, acc[mt][nt][1] * sc, h0, l0);
                    split_pair(acc[mt][nt][2] * sc, acc[mt][nt][3] * sc, h1, l1);
                    *reinterpret_cast<unsigned*>(&Dh[(size_t)row0 * 2048 + col]) = h0;
                    *reinterpret_cast<unsigned*>(&Dl[(size_t)row0 * 2048 + col]) = l0;
                    *reinterpret_cast<unsigned*>(&Dh[(size_t)(row0 + 8) * 2048 + col]) = h1;
                    *reinterpret_cast<unsigned*>(&Dl[(size_t)(row0 + 8) * 2048 + col]) = l1;
                }
        } else {
            // V: transposed split write  g_Vt*[col][row]
            #pragma unroll
            for (int mt = 0; mt < 2; mt++)
                #pragma unroll
                for (int nt = 0; nt < 8; nt++) {
                    const int row0 = bm + wm + mt * 16 + fr;
                    const int col  = bn + wn + nt * 8 + 2 * fc;
                    #pragma unroll
                    for (int q = 0; q < 4; q++) {
                        const int rr = row0 + (q >> 1) * 8;
                        const int cc = col + (q & 1);
                        __half h, l;
                        split1(acc[mt][nt][q], h, l);
                        g_Vth[(size_t)cc * MROWS + rr] = h;
                        g_Vtl[(size_t)cc * MROWS + rr] = l;
                    }
                }
        }
        if (EPI == 0) __syncthreads();
    }
}

// ---------------------------------------------------------------------------
// Flash attention prefill, fp16 hi/lo 3-mma split, register softmax + reg m/l.
// 3 syncs per tile. All operands pre-split/pre-transposed in gmem.
// BQ=BK=64, 256 threads; warp pair shares 16 Q rows, splits 64 tokens.
// ---------------------------------------------------------------------------
#define FQS 136   // Q/K row stride (halves)
#define FVS 72    // Vt row stride (halves)

#define OFF_QH  0
#define OFF_QL  (OFF_QH + 64 * FQS * 2)
#define OFF_KH  (OFF_QL + 64 * FQS * 2)
#define OFF_KL  (OFF_KH + 64 * FQS * 2)
#define OFF_VTH (OFF_KL + 64 * FQS * 2)
#define OFF_VTL (OFF_VTH + 128 * FVS * 2)
#define OFF_PM  (OFF_VTL + 128 * FVS * 2)
#define OFF_PSUM (OFF_PM + 128 * 4)
#define FLASH_SMEM_BYTES (OFF_PSUM + 128 * 4)

__global__ __launch_bounds__(256) void flash_hmma_kernel()
{
    extern __shared__ char fsm[];
    __half* Qhs = reinterpret_cast<__half*>(fsm + OFF_QH);
    __half* Qls = reinterpret_cast<__half*>(fsm + OFF_QL);
    __half* Khs = reinterpret_cast<__half*>(fsm + OFF_KH);
    __half* Kls = reinterpret_cast<__half*>(fsm + OFF_KL);
    __half* Vhs = reinterpret_cast<__half*>(fsm + OFF_VTH);
    __half* Vls = reinterpret_cast<__half*>(fsm + OFF_VTL);
    float*  pm   = reinterpret_cast<float*>(fsm + OFF_PM);
    float*  psum = reinterpret_cast<float*>(fsm + OFF_PSUM);

    const int qi = blockIdx.x;
    const int n  = blockIdx.y;
    const int b  = blockIdx.z;
    const int tid  = threadIdx.x;
    const int lane = tid & 31;
    const int warp = tid >> 5;
    const int wm   = (warp >> 1) * 16;
    const int wh   = (warp & 1);
    const int fr   = lane >> 2;
    const int fc   = lane & 3;

    const int qk_r = tid >> 2;
    const int qk_c = (tid & 3) * 32;
    const int v_r = tid >> 1;
    const int v_c = (tid & 1) * 32;

    const size_t hcol = (size_t)n * HDIM;
    const int r0 = wm + fr, r1 = wm + fr + 8;

    // ---- load Q tile (pure copy; already scaled+split) ----
    {
        const size_t base = (size_t)(b * SEQ + qi * 64 + qk_r) * 2048 + hcol + qk_c;
        #pragma unroll
        for (int i = 0; i < 4; i++) {
            *reinterpret_cast<uint4*>(&Qhs[qk_r * FQS + qk_c + 8 * i]) =
                *reinterpret_cast<const uint4*>(&g_Qh[base + 8 * i]);
            *reinterpret_cast<uint4*>(&Qls[qk_r * FQS + qk_c + 8 * i]) =
                *reinterpret_cast<const uint4*>(&g_Ql[base + 8 * i]);
        }
    }

    // ---- K tile 0 -> smem; V tile 0 -> regs ----
    {
        const size_t base = (size_t)(b * SEQ + qk_r) * 2048 + hcol + qk_c;
        #pragma unroll
        for (int i = 0; i < 4; i++) {
            *reinterpret_cast<uint4*>(&Khs[qk_r * FQS + qk_c + 8 * i]) =
                *reinterpret_cast<const uint4*>(&g_Kh[base + 8 * i]);
            *reinterpret_cast<uint4*>(&Kls[qk_r * FQS + qk_c + 8 * i]) =
                *reinterpret_cast<const uint4*>(&g_Kl[base + 8 * i]);
        }
    }
    uint4 vrh[4], vrl[4];
    {
        const size_t base = (hcol + v_r) * (size_t)MROWS + b * SEQ + v_c;
        #pragma unroll
        for (int i = 0; i < 4; i++) {
            vrh[i] = *reinterpret_cast<const uint4*>(&g_Vth[base + 8 * i]);
            vrl[i] = *reinterpret_cast<const uint4*>(&g_Vtl[base + 8 * i]);
        }
    }
    __syncthreads();

    float o[16][4];
    #pragma unroll
    for (int i = 0; i < 16; i++)
        #pragma unroll
        for (int j = 0; j < 4; j++) o[i][j] = 0.f;

    float m0 = -INFINITY, m1 = -INFINITY, l0 = 0.f, l1 = 0.f;

    for (int kt = 0; kt <= qi; kt++) {
        // ---- 1. S = Q K^T over own 32 cols (fp16 3-mma split) ----
        float sacc[4][4];
        #pragma unroll
        for (int i = 0; i < 4; i++)
            #pragma unroll
            for (int j = 0; j < 4; j++) sacc[i][j] = 0.f;

        #pragma unroll
        for (int kc = 0; kc < 8; kc++) {
            const int kb = kc * 16 + 2 * fc;
            const int ar0 = r0 * FQS + kb;
            const int ar1 = r1 * FQS + kb;
            unsigned ah[4], al[4];
            ah[0] = *reinterpret_cast<const unsigned*>(&Qhs[ar0]);
            ah[1] = *reinterpret_cast<const unsigned*>(&Qhs[ar1]);
            ah[2] = *reinterpret_cast<const unsigned*>(&Qhs[ar0 + 8]);
            ah[3] = *reinterpret_cast<const unsigned*>(&Qhs[ar1 + 8]);
            al[0] = *reinterpret_cast<const unsigned*>(&Qls[ar0]);
            al[1] = *reinterpret_cast<const unsigned*>(&Qls[ar1]);
            al[2] = *reinterpret_cast<const unsigned*>(&Qls[ar0 + 8]);
            al[3] = *reinterpret_cast<const unsigned*>(&Qls[ar1 + 8]);
            #pragma unroll
            for (int nt = 0; nt < 4; nt++) {
                const int br = (wh * 32 + nt * 8 + fr) * FQS + kb;
                unsigned bh[2], bl[2];
                bh[0] = *reinterpret_cast<const unsigned*>(&Khs[br]);
                bh[1] = *reinterpret_cast<const unsigned*>(&Khs[br + 8]);
                bl[0] = *reinterpret_cast<const unsigned*>(&Kls[br]);
                bl[1] = *reinterpret_cast<const unsigned*>(&Kls[br + 8]);
                mma_f16(sacc[nt], ah, bh);
                mma_f16(sacc[nt], ah, bl);
                mma_f16(sacc[nt], al, bh);
            }
        }

        // ---- mask + own-half row max ----
        if (kt == qi) {
            #pragma unroll
            for (int nt = 0; nt < 4; nt++) {
                const int ct = wh * 32 + nt * 8 + 2 * fc;
                if (ct     > r0) sacc[nt][0] = -INFINITY;
                if (ct + 1 > r0) sacc[nt][1] = -INFINITY;
                if (ct     > r1) sacc[nt][2] = -INFINITY;
                if (ct + 1 > r1) sacc[nt][3] = -INFINITY;
            }
        }
        float mx0 = -INFINITY, mx1 = -INFINITY;
        #pragma unroll
        for (int nt = 0; nt < 4; nt++) {
            mx0 = fmaxf(mx0, fmaxf(sacc[nt][0], sacc[nt][1]));
            mx1 = fmaxf(mx1, fmaxf(sacc[nt][2], sacc[nt][3]));
        }
        mx0 = fmaxf(mx0, __shfl_xor_sync(0xffffffffu, mx0, 1));
        mx0 = fmaxf(mx0, __shfl_xor_sync(0xffffffffu, mx0, 2));
        mx1 = fmaxf(mx1, __shfl_xor_sync(0xffffffffu, mx1, 1));
        mx1 = fmaxf(mx1, __shfl_xor_sync(0xffffffffu, mx1, 2));

        // ---- exp with own-half max (clamped: all-masked half -> e = 0) ----
        const float mc0 = fmaxf(mx0, -1e30f);
        const float mc1 = fmaxf(mx1, -1e30f);
        float s0 = 0.f, s1 = 0.f;
        #pragma unroll
        for (int nt = 0; nt < 4; nt++) {
            sacc[nt][0] = __expf(sacc[nt][0] - mc0); s0 += sacc[nt][0];
            sacc[nt][1] = __expf(sacc[nt][1] - mc0); s0 += sacc[nt][1];
            sacc[nt][2] = __expf(sacc[nt][2] - mc1); s1 += sacc[nt][2];
            sacc[nt][3] = __expf(sacc[nt][3] - mc1); s1 += sacc[nt][3];
        }
        s0 += __shfl_xor_sync(0xffffffffu, s0, 1);
        s0 += __shfl_xor_sync(0xffffffffu, s0, 2);
        s1 += __shfl_xor_sync(0xffffffffu, s1, 1);
        s1 += __shfl_xor_sync(0xffffffffu, s1, 2);
        __syncthreads();   // sync1: prev PV done with Vt; Khs/Kls consumed

        // ---- 2. V regs -> Vt smem; (max, sum) exchange; prefetch next K ----
        #pragma unroll
        for (int i = 0; i < 4; i++) {
            *reinterpret_cast<uint4*>(&Vhs[v_r * FVS + v_c + 8 * i]) = vrh[i];
            *reinterpret_cast<uint4*>(&Vls[v_r * FVS + v_c + 8 * i]) = vrl[i];
        }
        if (fc == 0) {
            pm[wh * 64 + r0] = mx0;   pm[wh * 64 + r1] = mx1;
            psum[wh * 64 + r0] = s0;  psum[wh * 64 + r1] = s1;
        }
        uint4 krh[4], krl[4];
        if (kt < qi) {
            const size_t base = (size_t)(b * SEQ + (kt + 1) * 64 + qk_r) * 2048 + hcol + qk_c;
            #pragma unroll
            for (int i = 0; i < 4; i++) {
                krh[i] = *reinterpret_cast<const uint4*>(&g_Kh[base + 8 * i]);
                krl[i] = *reinterpret_cast<const uint4*>(&g_Kl[base + 8 * i]);
            }
        }
        __syncthreads();   // sync2: Vt, pm, psum visible

        // ---- 3. combine halves in registers; pack P with correction ----
        const float pa0 = pm[r0], pb0 = pm[64 + r0];
        const float pa1 = pm[r1], pb1 = pm[64 + r1];
        const float mn0 = fmaxf(m0, fmaxf(pa0, pb0));
        const float mn1 = fmaxf(m1, fmaxf(pa1, pb1));
        const float alpha0 = __expf(m0 - mn0);
        const float alpha1 = __expf(m1 - mn1);
        l0 = l0 * alpha0 + psum[r0] * __expf(pa0 - mn0) + psum[64 + r0] * __expf(pb0 - mn0);
        l1 = l1 * alpha1 + psum[r1] * __expf(pa1 - mn1) + psum[64 + r1] * __expf(pb1 - mn1);
        m0 = mn0; m1 = mn1;
        const float corr0 = __expf(mx0 - mn0);
        const float corr1 = __expf(mx1 - mn1);

        unsigned Pfh[2][4], Pfl[2][4];
        #pragma unroll
        for (int j = 0; j < 2; j++) {
            split_pair(sacc[2*j][0] * corr0,   sacc[2*j][1] * corr0,   Pfh[j][0], Pfl[j][0]);
            split_pair(sacc[2*j][2] * corr1,   sacc[2*j][3] * corr1,   Pfh[j][1], Pfl[j][1]);
            split_pair(sacc[2*j+1][0] * corr0, sacc[2*j+1][1] * corr0, Pfh[j][2], Pfl[j][2]);
            split_pair(sacc[2*j+1][2] * corr1, sacc[2*j+1][3] * corr1, Pfh[j][3], Pfl[j][3]);
        }

        // ---- 4. O*=alpha; K regs -> smem; V prefetch; PV mma ----
        #pragma unroll
        for (int nt = 0; nt < 16; nt++) {
            o[nt][0] *= alpha0; o[nt][1] *= alpha0;
            o[nt][2] *= alpha1; o[nt][3] *= alpha1;
        }
        if (kt < qi) {
            #pragma unroll
            for (int i = 0; i < 4; i++) {
                *reinterpret_cast<uint4*>(&Khs[qk_r * FQS + qk_c + 8 * i]) = krh[i];
                *reinterpret_cast<uint4*>(&Kls[qk_r * FQS + qk_c + 8 * i]) = krl[i];
            }
            const size_t base = (hcol + v_r) * (size_t)MROWS + b * SEQ + (kt + 1) * 64 + v_c;
            #pragma unroll
            for (int i = 0; i < 4; i++) {
                vrh[i] = *reinterpret_cast<const uint4*>(&g_Vth[base + 8 * i]);
                vrl[i] = *reinterpret_cast<const uint4*>(&g_Vtl[base + 8 * i]);
            }
        }
        #pragma unroll
        for (int j = 0; j < 2; j++) {
            const int w = wh * 2 + j;       // 16-token window
            #pragma unroll
            for (int nt = 0; nt < 16; nt++) {
                const int br = (nt * 8 + fr) * FVS + w * 16 + 2 * fc;
                unsigned bh[2], bl[2];
                bh[0] = *reinterpret_cast<const unsigned*>(&Vhs[br]);
                bh[1] = *reinterpret_cast<const unsigned*>(&Vhs[br + 8]);
                bl[0] = *reinterpret_cast<const unsigned*>(&Vls[br]);
                bl[1] = *reinterpret_cast<const unsigned*>(&Vls[br + 8]);
                mma_f16(o[nt], Pfh[j], bh);
                mma_f16(o[nt], Pfh[j], bl);
                mma_f16(o[nt], Pfl[j], bh);
            }
        }
        __syncthreads();   // sync3: K store visible; Vt consumed
    }

    // ---- epilogue: merge partial O across warp pairs, write fp16 A ----
    float* Omrg = reinterpret_cast<float*>(fsm + OFF_KH);   // 32KB scratch
    if (wh == 1) {
        float* dst = &Omrg[((warp >> 1) * 32 + lane) * 64];
        #pragma unroll
        for (int nt = 0; nt < 16; nt++) {
            float4 v = make_float4(o[nt][0], o[nt][1], o[nt][2], o[nt][3]);
            *reinterpret_cast<float4*>(dst + nt * 4) = v;
        }
    }
    __syncthreads();
    if (wh == 0) {
        const float inv0 = 1.f / l0;
        const float inv1 = 1.f / l1;
        const float* src = &Omrg[((warp >> 1) * 32 + lane) * 64];
        __half* Ab = g_Ah + (size_t)(b * SEQ + qi * 64) * 2048 + hcol;
        #pragma unroll
        for (int nt = 0; nt < 16; nt++) {
            float4 v = *reinterpret_cast<const float4*>(src + nt * 4);
            const int col = nt * 8 + 2 * fc;
            __half2 p0 = __floats2half2_rn((o[nt][0] + v.x) * inv0, (o[nt][1] + v.y) * inv0);
            __half2 p1 = __floats2half2_rn((o[nt][2] + v.z) * inv1, (o[nt][3] + v.w) * inv1);
            *reinterpret_cast<__half2*>(&Ab[(size_t)r0 * 2048 + col]) = p0;
            *reinterpret_cast<__half2*>(&Ab[(size_t)r1 * 2048 + col]) = p1;
        }
    }
}

// ---------------------------------------------------------------------------
// Decode kernels
// ---------------------------------------------------------------------------
__global__ void decode_init_kernel()
{
    const int i = blockIdx.x * 256 + threadIdx.x;
    if (i < BATCH * D_MODEL) {
        g_q1[i] = 0.f; g_k1[i] = 0.f; g_v1[i] = 0.f;
    }
}

__global__ __launch_bounds__(256) void decode_proj_kernel(
    const float* __restrict__ xnew,
    const float* __restrict__ wq, const float* __restrict__ wk,
    const float* __restrict__ wv)
{
    const int col = blockIdx.x * 256 + threadIdx.x;
    const int b = blockIdx.y & 1;
    const int w = blockIdx.y >> 1;
    const int d0 = blockIdx.z * 256;
    const float* wsel = (w == 0) ? wq : (w == 1) ? wk : wv;
    float* osel = (w == 0) ? g_q1 : (w == 1) ? g_k1 : g_v1;

    __shared__ float xs[256];
    xs[threadIdx.x] = xnew[b * D_MODEL + d0 + threadIdx.x];
    __syncthreads();

    float acc = 0.f;
    #pragma unroll 8
    for (int d = 0; d < 256; d++)
        acc += xs[d] * wsel[(size_t)(d0 + d) * D_MODEL + col];
    atomicAdd(&osel[b * D_MODEL + col], acc);
}

__global__ __launch_bounds__(256) void decode_attn_kernel()
{
    const int n = blockIdx.x;
    const int b = blockIdx.y;
    const int tid = threadIdx.x;
    const int lane = tid & 31;
    const int warp = tid >> 5;

    __shared__ float qs[HDIM];
    __shared__ float sc[SEQ + 1];
    __shared__ float red[256];

    if (tid < HDIM) qs[tid] = g_q1[b * D_MODEL + n * HDIM + tid];
    __syncthreads();

    const float scale = QSCALE;
    const float4 qv = *reinterpret_cast<const float4*>(&qs[lane * 4]);

    for (int t = warp; t < SEQ + 1; t += 8) {
        float s;
        if (t < SEQ) {
            const size_t base = (size_t)(b * SEQ + t) * 2048 + n * HDIM + lane * 4;
            uint2 kh = *reinterpret_cast<const uint2*>(&g_Kh[base]);
            uint2 kl = *reinterpret_cast<const uint2*>(&g_Kl[base]);
            float2 h0 = __half22float2(*reinterpret_cast<__half2*>(&kh.x));
            float2 h1 = __half22float2(*reinterpret_cast<__half2*>(&kh.y));
            float2 l0 = __half22float2(*reinterpret_cast<__half2*>(&kl.x));
            float2 l1 = __half22float2(*reinterpret_cast<__half2*>(&kl.y));
            s = qv.x * (h0.x + l0.x) + qv.y * (h0.y + l0.y)
              + qv.z * (h1.x + l1.x) + qv.w * (h1.y + l1.y);
        } else {
            const float* kr = g_k1 + b * D_MODEL + n * HDIM;
            float4 kv = *reinterpret_cast<const float4*>(&kr[lane * 4]);
            s = qv.x * kv.x + qv.y * kv.y + qv.z * kv.z + qv.w * kv.w;
        }
        #pragma unroll
        for (int o = 16; o > 0; o >>= 1) s += __shfl_xor_sync(0xffffffffu, s, o);
        if (lane == 0) sc[t] = s * scale;
    }
    __syncthreads();

    float mx = -INFINITY;
    for (int t = tid; t < SEQ + 1; t += 256) mx = fmaxf(mx, sc[t]);
    red[tid] = mx;
    __syncthreads();
    for (int s = 128; s > 0; s >>= 1) {
        if (tid < s) red[tid] = fmaxf(red[tid], red[tid + s]);
        __syncthreads();
    }
    mx = red[0];
    __syncthreads();

    float sum = 0.f;
    for (int t = tid; t < SEQ + 1; t += 256) {
        float p = __expf(sc[t] - mx);
        sc[t] = p;
        sum += p;
    }
    red[tid] = sum;
    __syncthreads();
    for (int s = 128; s > 0; s >>= 1) {
        if (tid < s) red[tid] += red[tid + s];
        __syncthreads();
    }
    const float inv = 1.f / red[0];
    __syncthreads();

    // V accumulation: each thread streams 1024 contiguous tokens of one h
    const int h = tid & 127;
    const int hf = tid >> 7;
    const __half* vth = &g_Vth[(size_t)(n * HDIM + h) * MROWS + b * SEQ + hf * 1024];
    const __half* vtl = &g_Vtl[(size_t)(n * HDIM + h) * MROWS + b * SEQ + hf * 1024];
    const float* scp = &sc[hf * 1024];
    float acc = 0.f;
    for (int t = 0; t < 1024; t += 8) {
        uint4 vh = *reinterpret_cast<const uint4*>(&vth[t]);
        uint4 vl = *reinterpret_cast<const uint4*>(&vtl[t]);
        const __half2* ph = reinterpret_cast<const __half2*>(&vh);
        const __half2* pl = reinterpret_cast<const __half2*>(&vl);
        #pragma unroll
        for (int j = 0; j < 4; j++) {
            float2 fh = __half22float2(ph[j]);
            float2 fl = __half22float2(pl[j]);
            acc += scp[t + 2 * j] * (fh.x + fl.x) + scp[t + 2 * j + 1] * (fh.y + fl.y);
        }
    }
    if (hf == 0) acc += sc[SEQ] * g_v1[b * D_MODEL + n * HDIM + h];
    red[tid] = acc;
    __syncthreads();
    if (tid < 128)
        g_a1[b * D_MODEL + n * HDIM + tid] = (red[tid] + red[tid + 128]) * inv;
}

__global__ __launch_bounds__(256) void decode_out_kernel(
    const float* __restrict__ wo, float* __restrict__ out)
{
    const int gw = (blockIdx.x * 256 + threadIdx.x) >> 5;
    const int lane = threadIdx.x & 31;
    if (gw >= BATCH * D_MODEL) return;
    const int b = gw >> 11;
    const int d = gw & (D_MODEL - 1);

    const float* a = g_a1 + b * D_MODEL;
    const float* w = wo + (size_t)d * D_MODEL;
    float acc = 0.f;
    for (int k = lane * 4; k < D_MODEL; k += 128) {
        float4 av = *reinterpret_cast<const float4*>(a + k);
        float4 wv = *reinterpret_cast<const float4*>(w + k);
        acc += av.x * wv.x + av.y * wv.y + av.z * wv.z + av.w * wv.w;
    }
    #pragma unroll
    for (int o = 16; o > 0; o >>= 1) acc += __shfl_down_sync(0xffffffff, acc, o);
    if (lane == 0) out[PREFILL_ELEMS + b * D_MODEL + d] = acc;
}

// ---------------------------------------------------------------------------
extern "C" void kernel_launch(void* const* d_in, const int* in_sizes, int n_in,
                              void* d_out, int out_size)
{
    const float* x     = (const float*)d_in[0];
    const float* x_new = (const float*)d_in[1];
    const float* wq    = (const float*)d_in[2];
    const float* wk    = (const float*)d_in[3];
    const float* wv    = (const float*)d_in[4];
    const float* wo    = (const float*)d_in[5];
    float* out = (float*)d_out;

    __half *pxh, *pAh, *pwqt, *pwkt, *pwvt, *pwoh;
    cudaGetSymbolAddress((void**)&pxh,  g_xh);
    cudaGetSymbolAddress((void**)&pAh,  g_Ah);
    cudaGetSymbolAddress((void**)&pwqt, g_wqt);
    cudaGetSymbolAddress((void**)&pwkt, g_wkt);
    cudaGetSymbolAddress((void**)&pwvt, g_wvt);
    cudaGetSymbolAddress((void**)&pwoh, g_woh);

    cudaFuncSetAttribute(flash_hmma_kernel,
                         cudaFuncAttributeMaxDynamicSharedMemorySize, FLASH_SMEM_BYTES);

    // 0. one-time conversions
    convert_x_kernel<<<PREFILL_ELEMS / 4 / 256, 256>>>(x);
    convert_wo_kernel<<<(D_MODEL * D_MODEL) / 4 / 256, 256>>>(wo);
    dim3 wtg(64, 64, 3);
    convert_wt_kernel<<<wtg, 256>>>(wq, wk, wv);

    // 1. Fused Q/K/V projections (fp16-native, R11 config)
    hgemm_kernel<0><<<NPERSIST, 256>>>(pxh, pwqt, pwkt, pwvt, nullptr, 1536);

    // 2-3. decode init + projections
    decode_init_kernel<<<(BATCH * D_MODEL + 255) / 256, 256>>>();
    dim3 dpgrid(D_MODEL / 256, BATCH * 3, 8);
    decode_proj_kernel<<<dpgrid, 256>>>(x_new, wq, wk, wv);

    // 4. Prefill flash attention (3-sync, register m/l)
    dim3 fgrid(SEQ / 64, NHEADS, BATCH);
    flash_hmma_kernel<<<fgrid, 256, FLASH_SMEM_BYTES>>>();

    // 5. Output projection (fp16-native, R11 config)
    hgemm_kernel<1><<<NPERSIST, 256>>>(pAh, pwoh, pwoh, pwoh, out, 512);

    // 6-7. decode attention + output projection
    dim3 dagrid(NHEADS, BATCH);
    decode_attn_kernel<<<dagrid, 256>>>();
    decode_out_kernel<<<512, 256>>>(wo, out);
}

// round 14
// speedup vs baseline: 1.3138x; 1.0706x over previous
#include <cuda_runtime.h>
#include <cuda_fp16.h>
#include <cuda_bf16.h>
#include <math.h>

// ---------------------------------------------------------------------------
// AttentionDisaggregated: prefill (causal self-attn over S=2048) + 1-token decode
// B=2, S=2048, D_MODEL=2048, N_HEADS=16, HEAD_DIM=128
// Round 14: GEMM gmem->smem via cp.async (3-stage, 1 sync/chunk), frag-batched
// mma chains. Flash (R13 3-sync register-m/l) and decode unchanged.
// ---------------------------------------------------------------------------

#define D_MODEL 2048
#define SEQ     2048
#define BATCH   2
#define NHEADS  16
#define HDIM    128
#define MROWS   (BATCH * SEQ)          // 4096
#define PREFILL_ELEMS (BATCH * SEQ * D_MODEL)  // 8388608
#define QSCALE  0.08838834764831843f   // 1/sqrt(128)

// fp16 scratch (device globals -- allocation-free rule)
__device__ __half g_Qh[MROWS * D_MODEL];
__device__ __half g_Ql[MROWS * D_MODEL];
__device__ __half g_Kh[MROWS * D_MODEL];
__device__ __half g_Kl[MROWS * D_MODEL];
__device__ __half g_Vth[D_MODEL * MROWS];  // transposed [col][row]
__device__ __half g_Vtl[D_MODEL * MROWS];
__device__ __half g_Ah[MROWS * D_MODEL];
__device__ __half g_xh[MROWS * D_MODEL];
__device__ __half g_wqt[D_MODEL * D_MODEL];  // [n][k]
__device__ __half g_wkt[D_MODEL * D_MODEL];
__device__ __half g_wvt[D_MODEL * D_MODEL];
__device__ __half g_woh[D_MODEL * D_MODEL];  // [n][k]
// decode fp32 scratch
__device__ float g_q1[BATCH * D_MODEL];
__device__ float g_k1[BATCH * D_MODEL];
__device__ float g_v1[BATCH * D_MODEL];
__device__ float g_a1[BATCH * D_MODEL];

// ---------------------------------------------------------------------------
// helpers
// ---------------------------------------------------------------------------
__device__ __forceinline__ void mma_f16(float* c, const unsigned* a, const unsigned* b) {
    asm volatile(
        "mma.sync.aligned.m16n8k16.row.col.f32.f16.f16.f32 "
        "{%0,%1,%2,%3}, {%4,%5,%6,%7}, {%8,%9}, {%0,%1,%2,%3};\n"
        : "+f"(c[0]), "+f"(c[1]), "+f"(c[2]), "+f"(c[3])
        : "r"(a[0]), "r"(a[1]), "r"(a[2]), "r"(a[3]), "r"(b[0]), "r"(b[1]));
}

__device__ __forceinline__ unsigned smem_u32_of(const void* p) {
    unsigned a;
    asm("{ .reg .u64 t; cvta.to.shared.u64 t, %1; cvt.u32.u64 %0, t; }"
        : "=r"(a) : "l"(p));
    return a;
}

#define CP_ASYNC16(saddr, gptr) \
    asm volatile("cp.async.cg.shared.global [%0], [%1], 16;" \
                 :: "r"(saddr), "l"(gptr) : "memory")
#define CP_COMMIT() asm volatile("cp.async.commit_group;" ::: "memory")
#define CP_WAIT1()  asm volatile("cp.async.wait_group 1;" ::: "memory")
#define CP_WAIT0()  asm volatile("cp.async.wait_group 0;" ::: "memory")

__device__ __forceinline__ void split_pair(float x, float y, unsigned& hi, unsigned& lo) {
    __half hx = __float2half_rn(x), hy = __float2half_rn(y);
    __half lx = __float2half_rn(x - __half2float(hx));
    __half ly = __float2half_rn(y - __half2float(hy));
    __half2 h = __halves2half2(hx, hy), l = __halves2half2(lx, ly);
    hi = *reinterpret_cast<unsigned*>(&h);
    lo = *reinterpret_cast<unsigned*>(&l);
}

__device__ __forceinline__ void split1(float v, __half& h, __half& l) {
    h = __float2half_rn(v);
    l = __float2half_rn(v - __half2float(h));
}

// ---------------------------------------------------------------------------
// Conversion kernels (one-time, bandwidth-bound)
// ---------------------------------------------------------------------------
__global__ __launch_bounds__(256) void convert_x_kernel(const float* __restrict__ src)
{
    const int i = (blockIdx.x * 256 + threadIdx.x) * 4;
    float4 v = *reinterpret_cast<const float4*>(src + i);
    __half2 a = __floats2half2_rn(v.x, v.y);
    __half2 b = __floats2half2_rn(v.z, v.w);
    *reinterpret_cast<__half2*>(&g_xh[i]) = a;
    *reinterpret_cast<__half2*>(&g_xh[i + 2]) = b;
}

__global__ __launch_bounds__(256) void convert_wo_kernel(const float* __restrict__ src)
{
    const int i = (blockIdx.x * 256 + threadIdx.x) * 4;
    float4 v = *reinterpret_cast<const float4*>(src + i);
    __half2 a = __floats2half2_rn(v.x, v.y);
    __half2 b = __floats2half2_rn(v.z, v.w);
    *reinterpret_cast<__half2*>(&g_woh[i]) = a;
    *reinterpret_cast<__half2*>(&g_woh[i + 2]) = b;
}

// transpose-convert wq/wk/wv [k][n] fp32 -> [n][k] fp16
__global__ __launch_bounds__(256) void convert_wt_kernel(
    const float* __restrict__ wq, const float* __restrict__ wk, const float* __restrict__ wv)
{
    __shared__ float ts[32][33];
    const int z = blockIdx.z;
    const float* src = (z == 0) ? wq : (z == 1) ? wk : wv;
    __half* dst = (z == 0) ? g_wqt : (z == 1) ? g_wkt : g_wvt;
    const int bx = blockIdx.x * 32;
    const int by = blockIdx.y * 32;
    const int tx = threadIdx.x & 31;
    const int ty = threadIdx.x >> 5;
    #pragma unroll
    for (int i = 0; i < 4; i++)
        ts[ty + 8 * i][tx] = src[(size_t)(by + ty + 8 * i) * 2048 + bx + tx];
    __syncthreads();
    #pragma unroll
    for (int i = 0; i < 4; i++)
        dst[(size_t)(bx + ty + 8 * i) * 2048 + by + tx] = __float2half_rn(ts[tx][ty + 8 * i]);
}

// ---------------------------------------------------------------------------
// Persistent fp16 HMMA GEMM (TT): C[M,N] = A[M,K] @ B[N,K]^T, halves in.
// BM=BN=128, BK=32, 256 threads, 8 warps each 32x64.
// cp.async 3-stage pipeline, one __syncthreads per chunk, batched fragments.
// EPI=0: QKV epilogue; EPI=1: fp32 C.
// ---------------------------------------------------------------------------
#define GSTRIDE 40
#define NPERSIST 296
#define GEMM_TILE_HALVES (128 * GSTRIDE)          // 5120 halves = 10240 B
#define GEMM_SMEM_BYTES  (3 * GEMM_TILE_HALVES * 2 * 2)   // 61440

template <int EPI>
__global__ __launch_bounds__(256, 2) void hgemm_kernel(
    const __half* __restrict__ A,
    const __half* __restrict__ B0, const __half* __restrict__ B1, const __half* __restrict__ B2,
    float* __restrict__ Cout, int ntiles)
{
    extern __shared__ __half gsm[];
    __half* As = gsm;                              // 3 stages
    __half* Bs = gsm + 3 * GEMM_TILE_HALVES;

    const int tid  = threadIdx.x;
    const int lane = tid & 31;
    const int warp = tid >> 5;
    const int wm   = (warp >> 1) * 32;
    const int wn   = (warp & 1) * 64;
    const int fr   = lane >> 2;
    const int fc   = lane & 3;

    const int l_r = tid >> 1;
    const int l_k = (tid & 1) * 16;

    const unsigned sAu = smem_u32_of(As) + (l_r * GSTRIDE + l_k) * 2;
    const unsigned sBu = smem_u32_of(Bs) + (l_r * GSTRIDE + l_k) * 2;

    for (int t = blockIdx.x; t < ntiles; t += NPERSIST) {
        const int z  = (EPI == 0) ? (t >> 9) : 0;
        const int r  = t & 511;
        const int bm = (r >> 4) * 128;
        const int bn = (r & 15) * 128;

        const __half* Bg = (z == 0) ? B0 : (z == 1) ? B1 : B2;
        const __half* gA = &A[(size_t)(bm + l_r) * 2048 + l_k];
        const __half* gB = &Bg[(size_t)(bn + l_r) * 2048 + l_k];

        float acc[2][8][4];
        #pragma unroll
        for (int i = 0; i < 2; i++)
            #pragma unroll
            for (int j = 0; j < 8; j++)
                #pragma unroll
                for (int q = 0; q < 4; q++) acc[i][j][q] = 0.f;

        auto cp_issue = [&](int k0, int sb) {
            const unsigned sa = sAu + sb * GEMM_TILE_HALVES * 2;
            const unsigned sbb = sBu + sb * GEMM_TILE_HALVES * 2;
            CP_ASYNC16(sa,       gA + k0);
            CP_ASYNC16(sa + 16,  gA + k0 + 8);
            CP_ASYNC16(sbb,      gB + k0);
            CP_ASYNC16(sbb + 16, gB + k0 + 8);
            CP_COMMIT();
        };

        cp_issue(0, 0);
        cp_issue(32, 1);

        int buf = 0;
        for (int c = 0; c < 64; c++) {
            if (c < 63) CP_WAIT1(); else CP_WAIT0();
            __syncthreads();
            if (c + 2 < 64) cp_issue((c + 2) * 32, (buf + 2) % 3);

            const __half* Ab = As + buf * GEMM_TILE_HALVES;
            const __half* Bb = Bs + buf * GEMM_TILE_HALVES;
            #pragma unroll
            for (int ks = 0; ks < 2; ks++) {
                const int kk = ks * 16 + 2 * fc;
                unsigned afr[2][4];
                #pragma unroll
                for (int mt = 0; mt < 2; mt++) {
                    const int m0 = (wm + mt * 16) * GSTRIDE + kk;
                    afr[mt][0] = *reinterpret_cast<const unsigned*>(&Ab[m0 + fr * GSTRIDE]);
                    afr[mt][1] = *reinterpret_cast<const unsigned*>(&Ab[m0 + (fr + 8) * GSTRIDE]);
                    afr[mt][2] = *reinterpret_cast<const unsigned*>(&Ab[m0 + fr * GSTRIDE + 8]);
                    afr[mt][3] = *reinterpret_cast<const unsigned*>(&Ab[m0 + (fr + 8) * GSTRIDE + 8]);
                }
                unsigned bfr[8][2];
                #pragma unroll
                for (int nt = 0; nt < 8; nt++) {
                    const int n0 = (wn + nt * 8 + fr) * GSTRIDE + kk;
                    bfr[nt][0] = *reinterpret_cast<const unsigned*>(&Bb[n0]);
                    bfr[nt][1] = *reinterpret_cast<const unsigned*>(&Bb[n0 + 8]);
                }
                #pragma unroll
                for (int nt = 0; nt < 8; nt++) {
                    mma_f16(acc[0][nt], afr[0], bfr[nt]);
                    mma_f16(acc[1][nt], afr[1], bfr[nt]);
                }
            }
            buf = (buf + 1) % 3;
        }

        // ---- epilogue ----
        if (EPI == 1) {
            #pragma unroll
            for (int mt = 0; mt < 2; mt++)
                #pragma unroll
                for (int nt = 0; nt < 8; nt++) {
                    const int row0 = bm + wm + mt * 16 + fr;
                    const int col  = bn + wn + nt * 8 + 2 * fc;
                    *reinterpret_cast<float2*>(&Cout[(size_t)row0 * 2048 + col]) =
                        make_float2(acc[mt][nt][0], acc[mt][nt][1]);
                    *reinterpret_cast<float2*>(&Cout[(size_t)(row0 + 8) * 2048 + col]) =
                        make_float2(acc[mt][nt][2], acc[mt][nt][3]);
                }
        } else if (z < 2) {
            __half* Dh = (z == 0) ? g_Qh : g_Kh;
            __half* Dl = (z == 0) ? g_Ql : g_Kl;
            const float sc = (z == 0) ? QSCALE : 1.f;
            #pragma unroll
            for (int mt = 0; mt < 2; mt++)
                #pragma unroll
                for (int nt = 0; nt < 8; nt++) {
                    const int row0 = bm + wm + mt * 16 + fr;
                    const int col  = bn + wn + nt * 8 + 2 * fc;
                    unsigned h0, l0, h1, l1;
                    split_pair(acc[mt][nt][0] * sc, acc[mt][nt][1] * sc, h0, l0);
                    split_pair(acc[mt][nt][2] * sc, acc[mt][nt][3] * sc, h1, l1);
                    *reinterpret_cast<unsigned*>(&Dh[(size_t)row0 * 2048 + col]) = h0;
                    *reinterpret_cast<unsigned*>(&Dl[(size_t)row0 * 2048 + col]) = l0;
                    *reinterpret_cast<unsigned*>(&Dh[(size_t)(row0 + 8) * 2048 + col]) = h1;
                    *reinterpret_cast<unsigned*>(&Dl[(size_t)(row0 + 8) * 2048 + col]) = l1;
                }
        } else {
            #pragma unroll
            for (int mt = 0; mt < 2; mt++)
                #pragma unroll
                for (int nt = 0; nt < 8; nt++) {
                    const int row0 = bm + wm + mt * 16 + fr;
                    const int col  = bn + wn + nt * 8 + 2 * fc;
                    #pragma unroll
                    for (int q = 0; q < 4; q++) {
                        const int rr = row0 + (q >> 1) * 8;
                        const int cc = col + (q & 1);
                        __half h, l;
                        split1(acc[mt][nt][q], h, l);
                        g_Vth[(size_t)cc * MROWS + rr] = h;
                        g_Vtl[(size_t)cc * MROWS + rr] = l;
                    }
                }
        }
        __syncthreads();   // all reads of stage buffers done before next tile's cp.async
    }
}

// ---------------------------------------------------------------------------
// Flash attention prefill (R13): fp16 hi/lo 3-mma split, register softmax+m/l,
// 3 syncs per tile. All operands pre-split/pre-transposed in gmem.
// ---------------------------------------------------------------------------
#define FQS 136
#define FVS 72

#define OFF_QH  0
#define OFF_QL  (OFF_QH + 64 * FQS * 2)
#define OFF_KH  (OFF_QL + 64 * FQS * 2)
#define OFF_KL  (OFF_KH + 64 * FQS * 2)
#define OFF_VTH (OFF_KL + 64 * FQS * 2)
#define OFF_VTL (OFF_VTH + 128 * FVS * 2)
#define OFF_PM  (OFF_VTL + 128 * FVS * 2)
#define OFF_PSUM (OFF_PM + 128 * 4)
#define FLASH_SMEM_BYTES (OFF_PSUM + 128 * 4)

__global__ __launch_bounds__(256) void flash_hmma_kernel()
{
    extern __shared__ char fsm[];
    __half* Qhs = reinterpret_cast<__half*>(fsm + OFF_QH);
    __half* Qls = reinterpret_cast<__half*>(fsm + OFF_QL);
    __half* Khs = reinterpret_cast<__half*>(fsm + OFF_KH);
    __half* Kls = reinterpret_cast<__half*>(fsm + OFF_KL);
    __half* Vhs = reinterpret_cast<__half*>(fsm + OFF_VTH);
    __half* Vls = reinterpret_cast<__half*>(fsm + OFF_VTL);
    float*  pm   = reinterpret_cast<float*>(fsm + OFF_PM);
    float*  psum = reinterpret_cast<float*>(fsm + OFF_PSUM);

    const int qi = blockIdx.x;
    const int n  = blockIdx.y;
    const int b  = blockIdx.z;
    const int tid  = threadIdx.x;
    const int lane = tid & 31;
    const int warp = tid >> 5;
    const int wm   = (warp >> 1) * 16;
    const int wh   = (warp & 1);
    const int fr   = lane >> 2;
    const int fc   = lane & 3;

    const int qk_r = tid >> 2;
    const int qk_c = (tid & 3) * 32;
    const int v_r = tid >> 1;
    const int v_c = (tid & 1) * 32;

    const size_t hcol = (size_t)n * HDIM;
    const int r0 = wm + fr, r1 = wm + fr + 8;

    {
        const size_t base = (size_t)(b * SEQ + qi * 64 + qk_r) * 2048 + hcol + qk_c;
        #pragma unroll
        for (int i = 0; i < 4; i++) {
            *reinterpret_cast<uint4*>(&Qhs[qk_r * FQS + qk_c + 8 * i]) =
                *reinterpret_cast<const uint4*>(&g_Qh[base + 8 * i]);
            *reinterpret_cast<uint4*>(&Qls[qk_r * FQS + qk_c + 8 * i]) =
                *reinterpret_cast<const uint4*>(&g_Ql[base + 8 * i]);
        }
    }
    {
        const size_t base = (size_t)(b * SEQ + qk_r) * 2048 + hcol + qk_c;
        #pragma unroll
        for (int i = 0; i < 4; i++) {
            *reinterpret_cast<uint4*>(&Khs[qk_r * FQS + qk_c + 8 * i]) =
                *reinterpret_cast<const uint4*>(&g_Kh[base + 8 * i]);
            *reinterpret_cast<uint4*>(&Kls[qk_r * FQS + qk_c + 8 * i]) =
                *reinterpret_cast<const uint4*>(&g_Kl[base + 8 * i]);
        }
    }
    uint4 vrh[4], vrl[4];
    {
        const size_t base = (hcol + v_r) * (size_t)MROWS + b * SEQ + v_c;
        #pragma unroll
        for (int i = 0; i < 4; i++) {
            vrh[i] = *reinterpret_cast<const uint4*>(&g_Vth[base + 8 * i]);
            vrl[i] = *reinterpret_cast<const uint4*>(&g_Vtl[base + 8 * i]);
        }
    }
    __syncthreads();

    float o[16][4];
    #pragma unroll
    for (int i = 0; i < 16; i++)
        #pragma unroll
        for (int j = 0; j < 4; j++) o[i][j] = 0.f;

    float m0 = -INFINITY, m1 = -INFINITY, l0 = 0.f, l1 = 0.f;

    for (int kt = 0; kt <= qi; kt++) {
        float sacc[4][4];
        #pragma unroll
        for (int i = 0; i < 4; i++)
            #pragma unroll
            for (int j = 0; j < 4; j++) sacc[i][j] = 0.f;

        #pragma unroll
        for (int kc = 0; kc < 8; kc++) {
            const int kb = kc * 16 + 2 * fc;
            const int ar0 = r0 * FQS + kb;
            const int ar1 = r1 * FQS + kb;
            unsigned ah[4], al[4];
            ah[0] = *reinterpret_cast<const unsigned*>(&Qhs[ar0]);
            ah[1] = *reinterpret_cast<const unsigned*>(&Qhs[ar1]);
            ah[2] = *reinterpret_cast<const unsigned*>(&Qhs[ar0 + 8]);
            ah[3] = *reinterpret_cast<const unsigned*>(&Qhs[ar1 + 8]);
            al[0] = *reinterpret_cast<const unsigned*>(&Qls[ar0]);
            al[1] = *reinterpret_cast<const unsigned*>(&Qls[ar1]);
            al[2] = *reinterpret_cast<const unsigned*>(&Qls[ar0 + 8]);
            al[3] = *reinterpret_cast<const unsigned*>(&Qls[ar1 + 8]);
            #pragma unroll
            for (int nt = 0; nt < 4; nt++) {
                const int br = (wh * 32 + nt * 8 + fr) * FQS + kb;
                unsigned bh[2], bl[2];
                bh[0] = *reinterpret_cast<const unsigned*>(&Khs[br]);
                bh[1] = *reinterpret_cast<const unsigned*>(&Khs[br + 8]);
                bl[0] = *reinterpret_cast<const unsigned*>(&Kls[br]);
                bl[1] = *reinterpret_cast<const unsigned*>(&Kls[br + 8]);
                mma_f16(sacc[nt], ah, bh);
                mma_f16(sacc[nt], ah, bl);
                mma_f16(sacc[nt], al, bh);
            }
        }

        if (kt == qi) {
            #pragma unroll
            for (int nt = 0; nt < 4; nt++) {
                const int ct = wh * 32 + nt * 8 + 2 * fc;
                if (ct     > r0) sacc[nt][0] = -INFINITY;
                if (ct + 1 > r0) sacc[nt][1] = -INFINITY;
                if (ct     > r1) sacc[nt][2] = -INFINITY;
                if (ct + 1 > r1) sacc[nt][3] = -INFINITY;
            }
        }
        float mx0 = -INFINITY, mx1 = -INFINITY;
        #pragma unroll
        for (int nt = 0; nt < 4; nt++) {
            mx0 = fmaxf(mx0, fmaxf(sacc[nt][0], sacc[nt][1]));
            mx1 = fmaxf(mx1, fmaxf(sacc[nt][2], sacc[nt][3]));
        }
        mx0 = fmaxf(mx0, __shfl_xor_sync(0xffffffffu, mx0, 1));
        mx0 = fmaxf(mx0, __shfl_xor_sync(0xffffffffu, mx0, 2));
        mx1 = fmaxf(mx1, __shfl_xor_sync(0xffffffffu, mx1, 1));
        mx1 = fmaxf(mx1, __shfl_xor_sync(0xffffffffu, mx1, 2));

        const float mc0 = fmaxf(mx0, -1e30f);
        const float mc1 = fmaxf(mx1, -1e30f);
        float s0 = 0.f, s1 = 0.f;
        #pragma unroll
        for (int nt = 0; nt < 4; nt++) {
            sacc[nt][0] = __expf(sacc[nt][0] - mc0); s0 += sacc[nt][0];
            sacc[nt][1] = __expf(sacc[nt][1] - mc0); s0 += sacc[nt][1];
            sacc[nt][2] = __expf(sacc[nt][2] - mc1); s1 += sacc[nt][2];
            sacc[nt][3] = __expf(sacc[nt][3] - mc1); s1 += sacc[nt][3];
        }
        s0 += __shfl_xor_sync(0xffffffffu, s0, 1);
        s0 += __shfl_xor_sync(0xffffffffu, s0, 2);
        s1 += __shfl_xor_sync(0xffffffffu, s1, 1);
        s1 += __shfl_xor_sync(0xffffffffu, s1, 2);
        __syncthreads();   // sync1

        #pragma unroll
        for (int i = 0; i < 4; i++) {
            *reinterpret_cast<uint4*>(&Vhs[v_r * FVS + v_c + 8 * i]) = vrh[i];
            *reinterpret_cast<uint4*>(&Vls[v_r * FVS + v_c + 8 * i]) = vrl[i];
        }
        if (fc == 0) {
            pm[wh * 64 + r0] = mx0;   pm[wh * 64 + r1] = mx1;
            psum[wh * 64 + r0] = s0;  psum[wh * 64 + r1] = s1;
        }
        uint4 krh[4], krl[4];
        if (kt < qi) {
            const size_t base = (size_t)(b * SEQ + (kt + 1) * 64 + qk_r) * 2048 + hcol + qk_c;
            #pragma unroll
            for (int i = 0; i < 4; i++) {
                krh[i] = *reinterpret_cast<const uint4*>(&g_Kh[base + 8 * i]);
                krl[i] = *reinterpret_cast<const uint4*>(&g_Kl[base + 8 * i]);
            }
        }
        __syncthreads();   // sync2

        const float pa0 = pm[r0], pb0 = pm[64 + r0];
        const float pa1 = pm[r1], pb1 = pm[64 + r1];
        const float mn0 = fmaxf(m0, fmaxf(pa0, pb0));
        const float mn1 = fmaxf(m1, fmaxf(pa1, pb1));
        const float alpha0 = __expf(m0 - mn0);
        const float alpha1 = __expf(m1 - mn1);
        l0 = l0 * alpha0 + psum[r0] * __expf(pa0 - mn0) + psum[64 + r0] * __expf(pb0 - mn0);
        l1 = l1 * alpha1 + psum[r1] * __expf(pa1 - mn1) + psum[64 + r1] * __expf(pb1 - mn1);
        m0 = mn0; m1 = mn1;
        const float corr0 = __expf(mx0 - mn0);
        const float corr1 = __expf(mx1 - mn1);

        unsigned Pfh[2][4], Pfl[2][4];
        #pragma unroll
        for (int j = 0; j < 2; j++) {
            split_pair(sacc[2*j][0] * corr0,   sacc[2*j][1] * corr0,   Pfh[j][0], Pfl[j][0]);
            split_pair(sacc[2*j][2] * corr1,   sacc[2*j][3] * corr1,   Pfh[j][1], Pfl[j][1]);
            split_pair(sacc[2*j+1][0] * corr0, sacc[2*j+1][1] * corr0, Pfh[j][2], Pfl[j][2]);
            split_pair(sacc[2*j+1][2] * corr1, sacc[2*j+1][3] * corr1, Pfh[j][3], Pfl[j][3]);
        }

        #pragma unroll
        for (int nt = 0; nt < 16; nt++) {
            o[nt][0] *= alpha0; o[nt][1] *= alpha0;
            o[nt][2] *= alpha1; o[nt][3] *= alpha1;
        }
        if (kt < qi) {
            #pragma unroll
            for (int i = 0; i < 4; i++) {
                *reinterpret_cast<uint4*>(&Khs[qk_r * FQS + qk_c + 8 * i]) = krh[i];
                *reinterpret_cast<uint4*>(&Kls[qk_r * FQS + qk_c + 8 * i]) = krl[i];
            }
            const size_t base = (hcol + v_r) * (size_t)MROWS + b * SEQ + (kt + 1) * 64 + v_c;
            #pragma unroll
            for (int i = 0; i < 4; i++) {
                vrh[i] = *reinterpret_cast<const uint4*>(&g_Vth[base + 8 * i]);
                vrl[i] = *reinterpret_cast<const uint4*>(&g_Vtl[base + 8 * i]);
            }
        }
        #pragma unroll
        for (int j = 0; j < 2; j++) {
            const int w = wh * 2 + j;
            #pragma unroll
            for (int nt = 0; nt < 16; nt++) {
                const int br = (nt * 8 + fr) * FVS + w * 16 + 2 * fc;
                unsigned bh[2], bl[2];
                bh[0] = *reinterpret_cast<const unsigned*>(&Vhs[br]);
                bh[1] = *reinterpret_cast<const unsigned*>(&Vhs[br + 8]);
                bl[0] = *reinterpret_cast<const unsigned*>(&Vls[br]);
                bl[1] = *reinterpret_cast<const unsigned*>(&Vls[br + 8]);
                mma_f16(o[nt], Pfh[j], bh);
                mma_f16(o[nt], Pfh[j], bl);
                mma_f16(o[nt], Pfl[j], bh);
            }
        }
        __syncthreads();   // sync3
    }

    float* Omrg = reinterpret_cast<float*>(fsm + OFF_KH);
    if (wh == 1) {
        float* dst = &Omrg[((warp >> 1) * 32 + lane) * 64];
        #pragma unroll
        for (int nt = 0; nt < 16; nt++) {
            float4 v = make_float4(o[nt][0], o[nt][1], o[nt][2], o[nt][3]);
            *reinterpret_cast<float4*>(dst + nt * 4) = v;
        }
    }
    __syncthreads();
    if (wh == 0) {
        const float inv0 = 1.f / l0;
        const float inv1 = 1.f / l1;
        const float* src = &Omrg[((warp >> 1) * 32 + lane) * 64];
        __half* Ab = g_Ah + (size_t)(b * SEQ + qi * 64) * 2048 + hcol;
        #pragma unroll
        for (int nt = 0; nt < 16; nt++) {
            float4 v = *reinterpret_cast<const float4*>(src + nt * 4);
            const int col = nt * 8 + 2 * fc;
            __half2 p0 = __floats2half2_rn((o[nt][0] + v.x) * inv0, (o[nt][1] + v.y) * inv0);
            __half2 p1 = __floats2half2_rn((o[nt][2] + v.z) * inv1, (o[nt][3] + v.w) * inv1);
            *reinterpret_cast<__half2*>(&Ab[(size_t)r0 * 2048 + col]) = p0;
            *reinterpret_cast<__half2*>(&Ab[(size_t)r1 * 2048 + col]) = p1;
        }
    }
}

// ---------------------------------------------------------------------------
// Decode kernels (R13)
// ---------------------------------------------------------------------------
__global__ void decode_init_kernel()
{
    const int i = blockIdx.x * 256 + threadIdx.x;
    if (i < BATCH * D_MODEL) {
        g_q1[i] = 0.f; g_k1[i] = 0.f; g_v1[i] = 0.f;
    }
}

__global__ __launch_bounds__(256) void decode_proj_kernel(
    const float* __restrict__ xnew,
    const float* __restrict__ wq, const float* __restrict__ wk,
    const float* __restrict__ wv)
{
    const int col = blockIdx.x * 256 + threadIdx.x;
    const int b = blockIdx.y & 1;
    const int w = blockIdx.y >> 1;
    const int d0 = blockIdx.z * 256;
    const float* wsel = (w == 0) ? wq : (w == 1) ? wk : wv;
    float* osel = (w == 0) ? g_q1 : (w == 1) ? g_k1 : g_v1;

    __shared__ float xs[256];
    xs[threadIdx.x] = xnew[b * D_MODEL + d0 + threadIdx.x];
    __syncthreads();

    float acc = 0.f;
    #pragma unroll 8
    for (int d = 0; d < 256; d++)
        acc += xs[d] * wsel[(size_t)(d0 + d) * D_MODEL + col];
    atomicAdd(&osel[b * D_MODEL + col], acc);
}

__global__ __launch_bounds__(256) void decode_attn_kernel()
{
    const int n = blockIdx.x;
    const int b = blockIdx.y;
    const int tid = threadIdx.x;
    const int lane = tid & 31;
    const int warp = tid >> 5;

    __shared__ float qs[HDIM];
    __shared__ float sc[SEQ + 1];
    __shared__ float red[256];

    if (tid < HDIM) qs[tid] = g_q1[b * D_MODEL + n * HDIM + tid];
    __syncthreads();

    const float scale = QSCALE;
    const float4 qv = *reinterpret_cast<const float4*>(&qs[lane * 4]);

    for (int t = warp; t < SEQ + 1; t += 8) {
        float s;
        if (t < SEQ) {
            const size_t base = (size_t)(b * SEQ + t) * 2048 + n * HDIM + lane * 4;
            uint2 kh = *reinterpret_cast<const uint2*>(&g_Kh[base]);
            uint2 kl = *reinterpret_cast<const uint2*>(&g_Kl[base]);
            float2 h0 = __half22float2(*reinterpret_cast<__half2*>(&kh.x));
            float2 h1 = __half22float2(*reinterpret_cast<__half2*>(&kh.y));
            float2 l0 = __half22float2(*reinterpret_cast<__half2*>(&kl.x));
            float2 l1 = __half22float2(*reinterpret_cast<__half2*>(&kl.y));
            s = qv.x * (h0.x + l0.x) + qv.y * (h0.y + l0.y)
              + qv.z * (h1.x + l1.x) + qv.w * (h1.y + l1.y);
        } else {
            const float* kr = g_k1 + b * D_MODEL + n * HDIM;
            float4 kv = *reinterpret_cast<const float4*>(&kr[lane * 4]);
            s = qv.x * kv.x + qv.y * kv.y + qv.z * kv.z + qv.w * kv.w;
        }
        #pragma unroll
        for (int o = 16; o > 0; o >>= 1) s += __shfl_xor_sync(0xffffffffu, s, o);
        if (lane == 0) sc[t] = s * scale;
    }
    __syncthreads();

    float mx = -INFINITY;
    for (int t = tid; t < SEQ + 1; t += 256) mx = fmaxf(mx, sc[t]);
    red[tid] = mx;
    __syncthreads();
    for (int s = 128; s > 0; s >>= 1) {
        if (tid < s) red[tid] = fmaxf(red[tid], red[tid + s]);
        __syncthreads();
    }
    mx = red[0];
    __syncthreads();

    float sum = 0.f;
    for (int t = tid; t < SEQ + 1; t += 256) {
        float p = __expf(sc[t] - mx);
        sc[t] = p;
        sum += p;
    }
    red[tid] = sum;
    __syncthreads();
    for (int s = 128; s > 0; s >>= 1) {
        if (tid < s) red[tid] += red[tid + s];
        __syncthreads();
    }
    const float inv = 1.f / red[0];
    __syncthreads();

    const int h = tid & 127;
    const int hf = tid >> 7;
    const __half* vth = &g_Vth[(size_t)(n * HDIM + h) * MROWS + b * SEQ + hf * 1024];
    const __half* vtl = &g_Vtl[(size_t)(n * HDIM + h) * MROWS + b * SEQ + hf * 1024];
    const float* scp = &sc[hf * 1024];
    float acc = 0.f;
    for (int t = 0; t < 1024; t += 8) {
        uint4 vh = *reinterpret_cast<const uint4*>(&vth[t]);
        uint4 vl = *reinterpret_cast<const uint4*>(&vtl[t]);
        const __half2* ph = reinterpret_cast<const __half2*>(&vh);
        const __half2* pl = reinterpret_cast<const __half2*>(&vl);
        #pragma unroll
        for (int j = 0; j < 4; j++) {
            float2 fh = __half22float2(ph[j]);
            float2 fl = __half22float2(pl[j]);
            acc += scp[t + 2 * j] * (fh.x + fl.x) + scp[t + 2 * j + 1] * (fh.y + fl.y);
        }
    }
    if (hf == 0) acc += sc[SEQ] * g_v1[b * D_MODEL + n * HDIM + h];
    red[tid] = acc;
    __syncthreads();
    if (tid < 128)
        g_a1[b * D_MODEL + n * HDIM + tid] = (red[tid] + red[tid + 128]) * inv;
}

__global__ __launch_bounds__(256) void decode_out_kernel(
    const float* __restrict__ wo, float* __restrict__ out)
{
    const int gw = (blockIdx.x * 256 + threadIdx.x) >> 5;
    const int lane = threadIdx.x & 31;
    if (gw >= BATCH * D_MODEL) return;
    const int b = gw >> 11;
    const int d = gw & (D_MODEL - 1);

    const float* a = g_a1 + b * D_MODEL;
    const float* w = wo + (size_t)d * D_MODEL;
    float acc = 0.f;
    for (int k = lane * 4; k < D_MODEL; k += 128) {
        float4 av = *reinterpret_cast<const float4*>(a + k);
        float4 wv = *reinterpret_cast<const float4*>(w + k);
        acc += av.x * wv.x + av.y * wv.y + av.z * wv.z + av.w * wv.w;
    }
    #pragma unroll
    for (int o = 16; o > 0; o >>= 1) acc += __shfl_down_sync(0xffffffff, acc, o);
    if (lane == 0) out[PREFILL_ELEMS + b * D_MODEL + d] = acc;
}

// ---------------------------------------------------------------------------
extern "C" void kernel_launch(void* const* d_in, const int* in_sizes, int n_in,
                              void* d_out, int out_size)
{
    const float* x     = (const float*)d_in[0];
    const float* x_new = (const float*)d_in[1];
    const float* wq    = (const float*)d_in[2];
    const float* wk    = (const float*)d_in[3];
    const float* wv    = (const float*)d_in[4];
    const float* wo    = (const float*)d_in[5];
    float* out = (float*)d_out;

    __half *pxh, *pAh, *pwqt, *pwkt, *pwvt, *pwoh;
    cudaGetSymbolAddress((void**)&pxh,  g_xh);
    cudaGetSymbolAddress((void**)&pAh,  g_Ah);
    cudaGetSymbolAddress((void**)&pwqt, g_wqt);
    cudaGetSymbolAddress((void**)&pwkt, g_wkt);
    cudaGetSymbolAddress((void**)&pwvt, g_wvt);
    cudaGetSymbolAddress((void**)&pwoh, g_woh);

    cudaFuncSetAttribute(flash_hmma_kernel,
                         cudaFuncAttributeMaxDynamicSharedMemorySize, FLASH_SMEM_BYTES);
    cudaFuncSetAttribute(hgemm_kernel<0>,
                         cudaFuncAttributeMaxDynamicSharedMemorySize, GEMM_SMEM_BYTES);
    cudaFuncSetAttribute(hgemm_kernel<1>,
                         cudaFuncAttributeMaxDynamicSharedMemorySize, GEMM_SMEM_BYTES);

    // 0. one-time conversions
    convert_x_kernel<<<PREFILL_ELEMS / 4 / 256, 256>>>(x);
    convert_wo_kernel<<<(D_MODEL * D_MODEL) / 4 / 256, 256>>>(wo);
    dim3 wtg(64, 64, 3);
    convert_wt_kernel<<<wtg, 256>>>(wq, wk, wv);

    // 1. Fused Q/K/V projections (cp.async 3-stage pipeline)
    hgemm_kernel<0><<<NPERSIST, 256, GEMM_SMEM_BYTES>>>(pxh, pwqt, pwkt, pwvt, nullptr, 1536);

    // 2-3. decode init + projections
    decode_init_kernel<<<(BATCH * D_MODEL + 255) / 256, 256>>>();
    dim3 dpgrid(D_MODEL / 256, BATCH * 3, 8);
    decode_proj_kernel<<<dpgrid, 256>>>(x_new, wq, wk, wv);

    // 4. Prefill flash attention
    dim3 fgrid(SEQ / 64, NHEADS, BATCH);
    flash_hmma_kernel<<<fgrid, 256, FLASH_SMEM_BYTES>>>();

    // 5. Output projection (cp.async 3-stage pipeline)
    hgemm_kernel<1><<<NPERSIST, 256, GEMM_SMEM_BYTES>>>(pAh, pwoh, pwoh, pwoh, out, 512);

    // 6-7. decode attention + output projection
    dim3 dagrid(NHEADS, BATCH);
    decode_attn_kernel<<<dagrid, 256>>>();
    decode_out_kernel<<<512, 256>>>(wo, out);
}

// round 17
// speedup vs baseline: 1.6040x; 1.2209x over previous
#include <cuda_runtime.h>
#include <cuda_fp16.h>
#include <cuda_bf16.h>
#include <math.h>

// ---------------------------------------------------------------------------
// AttentionDisaggregated: prefill (causal self-attn over S=2048) + 1-token decode
// B=2, S=2048, D_MODEL=2048, N_HEADS=16, HEAD_DIM=128
// Round 15: flash K/V tile loads via cp.async (FIFO group ledger, 3 syncs);
// decode chain forked onto a second stream (overlaps flash + out-proj).
// GEMM (R14 cp.async 3-stage) and decode kernels unchanged.
// ---------------------------------------------------------------------------

#define D_MODEL 2048
#define SEQ     2048
#define BATCH   2
#define NHEADS  16
#define HDIM    128
#define MROWS   (BATCH * SEQ)          // 4096
#define PREFILL_ELEMS (BATCH * SEQ * D_MODEL)  // 8388608
#define QSCALE  0.08838834764831843f   // 1/sqrt(128)

// fp16 scratch (device globals -- allocation-free rule)
__device__ __half g_Qh[MROWS * D_MODEL];
__device__ __half g_Ql[MROWS * D_MODEL];
__device__ __half g_Kh[MROWS * D_MODEL];
__device__ __half g_Kl[MROWS * D_MODEL];
__device__ __half g_Vth[D_MODEL * MROWS];  // transposed [col][row]
__device__ __half g_Vtl[D_MODEL * MROWS];
__device__ __half g_Ah[MROWS * D_MODEL];
__device__ __half g_xh[MROWS * D_MODEL];
__device__ __half g_wqt[D_MODEL * D_MODEL];  // [n][k]
__device__ __half g_wkt[D_MODEL * D_MODEL];
__device__ __half g_wvt[D_MODEL * D_MODEL];
__device__ __half g_woh[D_MODEL * D_MODEL];  // [n][k]
// decode fp32 scratch
__device__ float g_q1[BATCH * D_MODEL];
__device__ float g_k1[BATCH * D_MODEL];
__device__ float g_v1[BATCH * D_MODEL];
__device__ float g_a1[BATCH * D_MODEL];

// ---------------------------------------------------------------------------
// helpers
// ---------------------------------------------------------------------------
__device__ __forceinline__ void mma_f16(float* c, const unsigned* a, const unsigned* b) {
    asm volatile(
        "mma.sync.aligned.m16n8k16.row.col.f32.f16.f16.f32 "
        "{%0,%1,%2,%3}, {%4,%5,%6,%7}, {%8,%9}, {%0,%1,%2,%3};\n"
        : "+f"(c[0]), "+f"(c[1]), "+f"(c[2]), "+f"(c[3])
        : "r"(a[0]), "r"(a[1]), "r"(a[2]), "r"(a[3]), "r"(b[0]), "r"(b[1]));
}

__device__ __forceinline__ unsigned smem_u32_of(const void* p) {
    unsigned a;
    asm("{ .reg .u64 t; cvta.to.shared.u64 t, %1; cvt.u32.u64 %0, t; }"
        : "=r"(a) : "l"(p));
    return a;
}

#define CP_ASYNC16(saddr, gptr) \
    asm volatile("cp.async.cg.shared.global [%0], [%1], 16;" \
                 :: "r"(saddr), "l"(gptr) : "memory")
#define CP_COMMIT() asm volatile("cp.async.commit_group;" ::: "memory")
#define CP_WAIT1()  asm volatile("cp.async.wait_group 1;" ::: "memory")
#define CP_WAIT0()  asm volatile("cp.async.wait_group 0;" ::: "memory")

__device__ __forceinline__ void split_pair(float x, float y, unsigned& hi, unsigned& lo) {
    __half hx = __float2half_rn(x), hy = __float2half_rn(y);
    __half lx = __float2half_rn(x - __half2float(hx));
    __half ly = __float2half_rn(y - __half2float(hy));
    __half2 h = __halves2half2(hx, hy), l = __halves2half2(lx, ly);
    hi = *reinterpret_cast<unsigned*>(&h);
    lo = *reinterpret_cast<unsigned*>(&l);
}

__device__ __forceinline__ void split1(float v, __half& h, __half& l) {
    h = __float2half_rn(v);
    l = __float2half_rn(v - __half2float(h));
}

// ---------------------------------------------------------------------------
// Conversion kernels
// ---------------------------------------------------------------------------
__global__ __launch_bounds__(256) void convert_x_kernel(const float* __restrict__ src)
{
    const int i = (blockIdx.x * 256 + threadIdx.x) * 4;
    float4 v = *reinterpret_cast<const float4*>(src + i);
    __half2 a = __floats2half2_rn(v.x, v.y);
    __half2 b = __floats2half2_rn(v.z, v.w);
    *reinterpret_cast<__half2*>(&g_xh[i]) = a;
    *reinterpret_cast<__half2*>(&g_xh[i + 2]) = b;
}

__global__ __launch_bounds__(256) void convert_wo_kernel(const float* __restrict__ src)
{
    const int i = (blockIdx.x * 256 + threadIdx.x) * 4;
    float4 v = *reinterpret_cast<const float4*>(src + i);
    __half2 a = __floats2half2_rn(v.x, v.y);
    __half2 b = __floats2half2_rn(v.z, v.w);
    *reinterpret_cast<__half2*>(&g_woh[i]) = a;
    *reinterpret_cast<__half2*>(&g_woh[i + 2]) = b;
}

__global__ __launch_bounds__(256) void convert_wt_kernel(
    const float* __restrict__ wq, const float* __restrict__ wk, const float* __restrict__ wv)
{
    __shared__ float ts[32][33];
    const int z = blockIdx.z;
    const float* src = (z == 0) ? wq : (z == 1) ? wk : wv;
    __half* dst = (z == 0) ? g_wqt : (z == 1) ? g_wkt : g_wvt;
    const int bx = blockIdx.x * 32;
    const int by = blockIdx.y * 32;
    const int tx = threadIdx.x & 31;
    const int ty = threadIdx.x >> 5;
    #pragma unroll
    for (int i = 0; i < 4; i++)
        ts[ty + 8 * i][tx] = src[(size_t)(by + ty + 8 * i) * 2048 + bx + tx];
    __syncthreads();
    #pragma unroll
    for (int i = 0; i < 4; i++)
        dst[(size_t)(bx + ty + 8 * i) * 2048 + by + tx] = __float2half_rn(ts[tx][ty + 8 * i]);
}

// ---------------------------------------------------------------------------
// Persistent fp16 HMMA GEMM (R14): cp.async 3-stage, 256 thr, 32x64 warp tiles.
// ---------------------------------------------------------------------------
#define GSTRIDE 40
#define NPERSIST 296
#define GEMM_TILE_HALVES (128 * GSTRIDE)
#define GEMM_SMEM_BYTES  (3 * GEMM_TILE_HALVES * 2 * 2)   // 61440

template <int EPI>
__global__ __launch_bounds__(256, 2) void hgemm_kernel(
    const __half* __restrict__ A,
    const __half* __restrict__ B0, const __half* __restrict__ B1, const __half* __restrict__ B2,
    float* __restrict__ Cout, int ntiles)
{
    extern __shared__ __half gsm[];
    __half* As = gsm;
    __half* Bs = gsm + 3 * GEMM_TILE_HALVES;

    const int tid  = threadIdx.x;
    const int lane = tid & 31;
    const int warp = tid >> 5;
    const int wm   = (warp >> 1) * 32;
    const int wn   = (warp & 1) * 64;
    const int fr   = lane >> 2;
    const int fc   = lane & 3;

    const int l_r = tid >> 1;
    const int l_k = (tid & 1) * 16;

    const unsigned sAu = smem_u32_of(As) + (l_r * GSTRIDE + l_k) * 2;
    const unsigned sBu = smem_u32_of(Bs) + (l_r * GSTRIDE + l_k) * 2;

    for (int t = blockIdx.x; t < ntiles; t += NPERSIST) {
        const int z  = (EPI == 0) ? (t >> 9) : 0;
        const int r  = t & 511;
        const int bm = (r >> 4) * 128;
        const int bn = (r & 15) * 128;

        const __half* Bg = (z == 0) ? B0 : (z == 1) ? B1 : B2;
        const __half* gA = &A[(size_t)(bm + l_r) * 2048 + l_k];
        const __half* gB = &Bg[(size_t)(bn + l_r) * 2048 + l_k];

        float acc[2][8][4];
        #pragma unroll
        for (int i = 0; i < 2; i++)
            #pragma unroll
            for (int j = 0; j < 8; j++)
                #pragma unroll
                for (int q = 0; q < 4; q++) acc[i][j][q] = 0.f;

        auto cp_issue = [&](int k0, int sb) {
            const unsigned sa = sAu + sb * GEMM_TILE_HALVES * 2;
            const unsigned sbb = sBu + sb * GEMM_TILE_HALVES * 2;
            CP_ASYNC16(sa,       gA + k0);
            CP_ASYNC16(sa + 16,  gA + k0 + 8);
            CP_ASYNC16(sbb,      gB + k0);
            CP_ASYNC16(sbb + 16, gB + k0 + 8);
            CP_COMMIT();
        };

        cp_issue(0, 0);
        cp_issue(32, 1);

        int buf = 0;
        for (int c = 0; c < 64; c++) {
            if (c < 63) CP_WAIT1(); else CP_WAIT0();
            __syncthreads();
            if (c + 2 < 64) cp_issue((c + 2) * 32, (buf + 2) % 3);

            const __half* Ab = As + buf * GEMM_TILE_HALVES;
            const __half* Bb = Bs + buf * GEMM_TILE_HALVES;
            #pragma unroll
            for (int ks = 0; ks < 2; ks++) {
                const int kk = ks * 16 + 2 * fc;
                unsigned afr[2][4];
                #pragma unroll
                for (int mt = 0; mt < 2; mt++) {
                    const int m0 = (wm + mt * 16) * GSTRIDE + kk;
                    afr[mt][0] = *reinterpret_cast<const unsigned*>(&Ab[m0 + fr * GSTRIDE]);
                    afr[mt][1] = *reinterpret_cast<const unsigned*>(&Ab[m0 + (fr + 8) * GSTRIDE]);
                    afr[mt][2] = *reinterpret_cast<const unsigned*>(&Ab[m0 + fr * GSTRIDE + 8]);
                    afr[mt][3] = *reinterpret_cast<const unsigned*>(&Ab[m0 + (fr + 8) * GSTRIDE + 8]);
                }
                unsigned bfr[8][2];
                #pragma unroll
                for (int nt = 0; nt < 8; nt++) {
                    const int n0 = (wn + nt * 8 + fr) * GSTRIDE + kk;
                    bfr[nt][0] = *reinterpret_cast<const unsigned*>(&Bb[n0]);
                    bfr[nt][1] = *reinterpret_cast<const unsigned*>(&Bb[n0 + 8]);
                }
                #pragma unroll
                for (int nt = 0; nt < 8; nt++) {
                    mma_f16(acc[0][nt], afr[0], bfr[nt]);
                    mma_f16(acc[1][nt], afr[1], bfr[nt]);
                }
            }
            buf = (buf + 1) % 3;
        }

        if (EPI == 1) {
            #pragma unroll
            for (int mt = 0; mt < 2; mt++)
                #pragma unroll
                for (int nt = 0; nt < 8; nt++) {
                    const int row0 = bm + wm + mt * 16 + fr;
                    const int col  = bn + wn + nt * 8 + 2 * fc;
                    *reinterpret_cast<float2*>(&Cout[(size_t)row0 * 2048 + col]) =
                        make_float2(acc[mt][nt][0], acc[mt][nt][1]);
                    *reinterpret_cast<float2*>(&Cout[(size_t)(row0 + 8) * 2048 + col]) =
                        make_float2(acc[mt][nt][2], acc[mt][nt][3]);
                }
        } else if (z < 2) {
            __half* Dh = (z == 0) ? g_Qh : g_Kh;
            __half* Dl = (z == 0) ? g_Ql : g_Kl;
            const float sc = (z == 0) ? QSCALE : 1.f;
            #pragma unroll
            for (int mt = 0; mt < 2; mt++)
                #pragma unroll
                for (int nt = 0; nt < 8; nt++) {
                    const int row0 = bm + wm + mt * 16 + fr;
                    const int col  = bn + wn + nt * 8 + 2 * fc;
                    unsigned h0, l0, h1, l1;
                    split_pair(acc[mt][nt][0] * sc, acc[mt][nt][1] * sc, h0, l0);
                    split_pair(acc[mt][nt][2] * sc, acc[mt][nt][3] * sc, h1, l1);
                    *reinterpret_cast<unsigned*>(&Dh[(size_t)row0 * 2048 + col]) = h0;
                    *reinterpret_cast<unsigned*>(&Dl[(size_t)row0 * 2048 + col]) = l0;
                    *reinterpret_cast<unsigned*>(&Dh[(size_t)(row0 + 8) * 2048 + col]) = h1;
                    *reinterpret_cast<unsigned*>(&Dl[(size_t)(row0 + 8) * 2048 + col]) = l1;
                }
        } else {
            #pragma unroll
            for (int mt = 0; mt < 2; mt++)
                #pragma unroll
                for (int nt = 0; nt < 8; nt++) {
                    const int row0 = bm + wm + mt * 16 + fr;
                    const int col  = bn + wn + nt * 8 + 2 * fc;
                    #pragma unroll
                    for (int q = 0; q < 4; q++) {
                        const int rr = row0 + (q >> 1) * 8;
                        const int cc = col + (q & 1);
                        __half h, l;
                        split1(acc[mt][nt][q], h, l);
                        g_Vth[(size_t)cc * MROWS + rr] = h;
                        g_Vtl[(size_t)cc * MROWS + rr] = l;
                    }
                }
        }
        __syncthreads();
    }
}

// ---------------------------------------------------------------------------
// Flash attention prefill: fp16 hi/lo 3-mma split, register softmax + m/l,
// cp.async K/V tile loads (FIFO ledger: V waits at WAIT1, K at WAIT0).
// 3 syncs per tile. BQ=BK=64, 256 threads.
// ---------------------------------------------------------------------------
#define FQS 136
#define FVS 72

#define OFF_QH  0
#define OFF_QL  (OFF_QH + 64 * FQS * 2)
#define OFF_KH  (OFF_QL + 64 * FQS * 2)
#define OFF_KL  (OFF_KH + 64 * FQS * 2)
#define OFF_VTH (OFF_KL + 64 * FQS * 2)
#define OFF_VTL (OFF_VTH + 128 * FVS * 2)
#define OFF_PM  (OFF_VTL + 128 * FVS * 2)
#define OFF_PSUM (OFF_PM + 128 * 4)
#define FLASH_SMEM_BYTES (OFF_PSUM + 128 * 4)

__global__ __launch_bounds__(256) void flash_hmma_kernel()
{
    extern __shared__ char fsm[];
    __half* Qhs = reinterpret_cast<__half*>(fsm + OFF_QH);
    __half* Qls = reinterpret_cast<__half*>(fsm + OFF_QL);
    __half* Khs = reinterpret_cast<__half*>(fsm + OFF_KH);
    __half* Kls = reinterpret_cast<__half*>(fsm + OFF_KL);
    __half* Vhs = reinterpret_cast<__half*>(fsm + OFF_VTH);
    __half* Vls = reinterpret_cast<__half*>(fsm + OFF_VTL);
    float*  pm   = reinterpret_cast<float*>(fsm + OFF_PM);
    float*  psum = reinterpret_cast<float*>(fsm + OFF_PSUM);

    const int qi = blockIdx.x;
    const int n  = blockIdx.y;
    const int b  = blockIdx.z;
    const int tid  = threadIdx.x;
    const int lane = tid & 31;
    const int warp = tid >> 5;
    const int wm   = (warp >> 1) * 16;
    const int wh   = (warp & 1);
    const int fr   = lane >> 2;
    const int fc   = lane & 3;

    const int qk_r = tid >> 2;
    const int qk_c = (tid & 3) * 32;
    const int v_r = tid >> 1;
    const int v_c = (tid & 1) * 32;

    const size_t hcol = (size_t)n * HDIM;
    const int r0 = wm + fr, r1 = wm + fr + 8;

    const unsigned smb = smem_u32_of(fsm);
    const unsigned sKh = smb + OFF_KH + (qk_r * FQS + qk_c) * 2;
    const unsigned sKl = smb + OFF_KL + (qk_r * FQS + qk_c) * 2;
    const unsigned sVh = smb + OFF_VTH + (v_r * FVS + v_c) * 2;
    const unsigned sVl = smb + OFF_VTL + (v_r * FVS + v_c) * 2;

    auto issue_K = [&](int kt) {
        const __half* kh = &g_Kh[(size_t)(b * SEQ + kt * 64 + qk_r) * 2048 + hcol + qk_c];
        const __half* kl = &g_Kl[(size_t)(b * SEQ + kt * 64 + qk_r) * 2048 + hcol + qk_c];
        #pragma unroll
        for (int i = 0; i < 4; i++) {
            CP_ASYNC16(sKh + 16 * i, kh + 8 * i);
            CP_ASYNC16(sKl + 16 * i, kl + 8 * i);
        }
        CP_COMMIT();
    };
    auto issue_V = [&](int kt) {
        const __half* vh = &g_Vth[(hcol + v_r) * (size_t)MROWS + b * SEQ + kt * 64 + v_c];
        const __half* vl = &g_Vtl[(hcol + v_r) * (size_t)MROWS + b * SEQ + kt * 64 + v_c];
        #pragma unroll
        for (int i = 0; i < 4; i++) {
            CP_ASYNC16(sVh + 16 * i, vh + 8 * i);
            CP_ASYNC16(sVl + 16 * i, vl + 8 * i);
        }
        CP_COMMIT();
    };

    // ---- pre-loop: K(0) async; Q tile copy ----
    issue_K(0);
    {
        const size_t base = (size_t)(b * SEQ + qi * 64 + qk_r) * 2048 + hcol + qk_c;
        #pragma unroll
        for (int i = 0; i < 4; i++) {
            *reinterpret_cast<uint4*>(&Qhs[qk_r * FQS + qk_c + 8 * i]) =
                *reinterpret_cast<const uint4*>(&g_Qh[base + 8 * i]);
            *reinterpret_cast<uint4*>(&Qls[qk_r * FQS + qk_c + 8 * i]) =
                *reinterpret_cast<const uint4*>(&g_Ql[base + 8 * i]);
        }
    }
    CP_WAIT0();
    __syncthreads();

    float o[16][4];
    #pragma unroll
    for (int i = 0; i < 16; i++)
        #pragma unroll
        for (int j = 0; j < 4; j++) o[i][j] = 0.f;

    float m0 = -INFINITY, m1 = -INFINITY, l0 = 0.f, l1 = 0.f;

    for (int kt = 0; kt <= qi; kt++) {
        // top: start V(kt) into Vhs/Vls (prev PV finished at sync C)
        issue_V(kt);

        // ---- S = Q K^T (Khs ready from prior WAIT0 + sync C) ----
        float sacc[4][4];
        #pragma unroll
        for (int i = 0; i < 4; i++)
            #pragma unroll
            for (int j = 0; j < 4; j++) sacc[i][j] = 0.f;

        #pragma unroll
        for (int kc = 0; kc < 8; kc++) {
            const int kb = kc * 16 + 2 * fc;
            const int ar0 = r0 * FQS + kb;
            const int ar1 = r1 * FQS + kb;
            unsigned ah[4], al[4];
            ah[0] = *reinterpret_cast<const unsigned*>(&Qhs[ar0]);
            ah[1] = *reinterpret_cast<const unsigned*>(&Qhs[ar1]);
            ah[2] = *reinterpret_cast<const unsigned*>(&Qhs[ar0 + 8]);
            ah[3] = *reinterpret_cast<const unsigned*>(&Qhs[ar1 + 8]);
            al[0] = *reinterpret_cast<const unsigned*>(&Qls[ar0]);
            al[1] = *reinterpret_cast<const unsigned*>(&Qls[ar1]);
            al[2] = *reinterpret_cast<const unsigned*>(&Qls[ar0 + 8]);
            al[3] = *reinterpret_cast<const unsigned*>(&Qls[ar1 + 8]);
            #pragma unroll
            for (int nt = 0; nt < 4; nt++) {
                const int br = (wh * 32 + nt * 8 + fr) * FQS + kb;
                unsigned bh[2], bl[2];
                bh[0] = *reinterpret_cast<const unsigned*>(&Khs[br]);
                bh[1] = *reinterpret_cast<const unsigned*>(&Khs[br + 8]);
                bl[0] = *reinterpret_cast<const unsigned*>(&Kls[br]);
                bl[1] = *reinterpret_cast<const unsigned*>(&Kls[br + 8]);
                mma_f16(sacc[nt], ah, bh);
                mma_f16(sacc[nt], ah, bl);
                mma_f16(sacc[nt], al, bh);
            }
        }

        // ---- mask + own-half max + exp + sums (registers) ----
        if (kt == qi) {
            #pragma unroll
            for (int nt = 0; nt < 4; nt++) {
                const int ct = wh * 32 + nt * 8 + 2 * fc;
                if (ct     > r0) sacc[nt][0] = -INFINITY;
                if (ct + 1 > r0) sacc[nt][1] = -INFINITY;
                if (ct     > r1) sacc[nt][2] = -INFINITY;
                if (ct + 1 > r1) sacc[nt][3] = -INFINITY;
            }
        }
        float mx0 = -INFINITY, mx1 = -INFINITY;
        #pragma unroll
        for (int nt = 0; nt < 4; nt++) {
            mx0 = fmaxf(mx0, fmaxf(sacc[nt][0], sacc[nt][1]));
            mx1 = fmaxf(mx1, fmaxf(sacc[nt][2], sacc[nt][3]));
        }
        mx0 = fmaxf(mx0, __shfl_xor_sync(0xffffffffu, mx0, 1));
        mx0 = fmaxf(mx0, __shfl_xor_sync(0xffffffffu, mx0, 2));
        mx1 = fmaxf(mx1, __shfl_xor_sync(0xffffffffu, mx1, 1));
        mx1 = fmaxf(mx1, __shfl_xor_sync(0xffffffffu, mx1, 2));

        const float mc0 = fmaxf(mx0, -1e30f);
        const float mc1 = fmaxf(mx1, -1e30f);
        float s0 = 0.f, s1 = 0.f;
        #pragma unroll
        for (int nt = 0; nt < 4; nt++) {
            sacc[nt][0] = __expf(sacc[nt][0] - mc0); s0 += sacc[nt][0];
            sacc[nt][1] = __expf(sacc[nt][1] - mc0); s0 += sacc[nt][1];
            sacc[nt][2] = __expf(sacc[nt][2] - mc1); s1 += sacc[nt][2];
            sacc[nt][3] = __expf(sacc[nt][3] - mc1); s1 += sacc[nt][3];
        }
        s0 += __shfl_xor_sync(0xffffffffu, s0, 1);
        s0 += __shfl_xor_sync(0xffffffffu, s0, 2);
        s1 += __shfl_xor_sync(0xffffffffu, s1, 1);
        s1 += __shfl_xor_sync(0xffffffffu, s1, 2);
        __syncthreads();   // sync A: S-reads of Khs done everywhere

        // ---- start K(kt+1); publish (max, sum) ----
        if (kt < qi) issue_K(kt + 1);
        if (fc == 0) {
            pm[wh * 64 + r0] = mx0;   pm[wh * 64 + r1] = mx1;
            psum[wh * 64 + r0] = s0;  psum[wh * 64 + r1] = s1;
        }
        CP_WAIT1();        // FIFO: waits V(kt) (older); K(kt+1) may stay in flight
        __syncthreads();   // sync B: Vt + pm + psum visible

        // ---- combine halves in registers; pack P; O*=alpha; PV ----
        const float pa0 = pm[r0], pb0 = pm[64 + r0];
        const float pa1 = pm[r1], pb1 = pm[64 + r1];
        const float mn0 = fmaxf(m0, fmaxf(pa0, pb0));
        const float mn1 = fmaxf(m1, fmaxf(pa1, pb1));
        const float alpha0 = __expf(m0 - mn0);
        const float alpha1 = __expf(m1 - mn1);
        l0 = l0 * alpha0 + psum[r0] * __expf(pa0 - mn0) + psum[64 + r0] * __expf(pb0 - mn0);
        l1 = l1 * alpha1 + psum[r1] * __expf(pa1 - mn1) + psum[64 + r1] * __expf(pb1 - mn1);
        m0 = mn0; m1 = mn1;
        const float corr0 = __expf(mx0 - mn0);
        const float corr1 = __expf(mx1 - mn1);

        unsigned Pfh[2][4], Pfl[2][4];
        #pragma unroll
        for (int j = 0; j < 2; j++) {
            split_pair(sacc[2*j][0] * corr0,   sacc[2*j][1] * corr0,   Pfh[j][0], Pfl[j][0]);
            split_pair(sacc[2*j][2] * corr1,   sacc[2*j][3] * corr1,   Pfh[j][1], Pfl[j][1]);
            split_pair(sacc[2*j+1][0] * corr0, sacc[2*j+1][1] * corr0, Pfh[j][2], Pfl[j][2]);
            split_pair(sacc[2*j+1][2] * corr1, sacc[2*j+1][3] * corr1, Pfh[j][3], Pfl[j][3]);
        }

        #pragma unroll
        for (int nt = 0; nt < 16; nt++) {
            o[nt][0] *= alpha0; o[nt][1] *= alpha0;
            o[nt][2] *= alpha1; o[nt][3] *= alpha1;
        }
        #pragma unroll
        for (int j = 0; j < 2; j++) {
            const int w = wh * 2 + j;
            #pragma unroll
            for (int nt = 0; nt < 16; nt++) {
                const int br = (nt * 8 + fr) * FVS + w * 16 + 2 * fc;
                unsigned bh[2], bl[2];
                bh[0] = *reinterpret_cast<const unsigned*>(&Vhs[br]);
                bh[1] = *reinterpret_cast<const unsigned*>(&Vhs[br + 8]);
                bl[0] = *reinterpret_cast<const unsigned*>(&Vls[br]);
                bl[1] = *reinterpret_cast<const unsigned*>(&Vls[br + 8]);
                mma_f16(o[nt], Pfh[j], bh);
                mma_f16(o[nt], Pfh[j], bl);
                mma_f16(o[nt], Pfl[j], bh);
            }
        }
        CP_WAIT0();        // K(kt+1) landed (had the whole PV phase)
        __syncthreads();   // sync C: K visible; Vt reads done
    }

    // ---- epilogue: merge partial O across warp pairs, write fp16 A ----
    float* Omrg = reinterpret_cast<float*>(fsm + OFF_KH);
    if (wh == 1) {
        float* dst = &Omrg[((warp >> 1) * 32 + lane) * 64];
        #pragma unroll
        for (int nt = 0; nt < 16; nt++) {
            float4 v = make_float4(o[nt][0], o[nt][1], o[nt][2], o[nt][3]);
            *reinterpret_cast<float4*>(dst + nt * 4) = v;
        }
    }
    __syncthreads();
    if (wh == 0) {
        const float inv0 = 1.f / l0;
        const float inv1 = 1.f / l1;
        const float* src = &Omrg[((warp >> 1) * 32 + lane) * 64];
        __half* Ab = g_Ah + (size_t)(b * SEQ + qi * 64) * 2048 + hcol;
        #pragma unroll
        for (int nt = 0; nt < 16; nt++) {
            float4 v = *reinterpret_cast<const float4*>(src + nt * 4);
            const int col = nt * 8 + 2 * fc;
            __half2 p0 = __floats2half2_rn((o[nt][0] + v.x) * inv0, (o[nt][1] + v.y) * inv0);
            __half2 p1 = __floats2half2_rn((o[nt][2] + v.z) * inv1, (o[nt][3] + v.w) * inv1);
            *reinterpret_cast<__half2*>(&Ab[(size_t)r0 * 2048 + col]) = p0;
            *reinterpret_cast<__half2*>(&Ab[(size_t)r1 * 2048 + col]) = p1;
        }
    }
}

// ---------------------------------------------------------------------------
// Decode kernels (R13)
// ---------------------------------------------------------------------------
__global__ void decode_init_kernel()
{
    const int i = blockIdx.x * 256 + threadIdx.x;
    if (i < BATCH * D_MODEL) {
        g_q1[i] = 0.f; g_k1[i] = 0.f; g_v1[i] = 0.f;
    }
}

__global__ __launch_bounds__(256) void decode_proj_kernel(
    const float* __restrict__ xnew,
    const float* __restrict__ wq, const float* __restrict__ wk,
    const float* __restrict__ wv)
{
    const int col = blockIdx.x * 256 + threadIdx.x;
    const int b = blockIdx.y & 1;
    const int w = blockIdx.y >> 1;
    const int d0 = blockIdx.z * 256;
    const float* wsel = (w == 0) ? wq : (w == 1) ? wk : wv;
    float* osel = (w == 0) ? g_q1 : (w == 1) ? g_k1 : g_v1;

    __shared__ float xs[256];
    xs[threadIdx.x] = xnew[b * D_MODEL + d0 + threadIdx.x];
    __syncthreads();

    float acc = 0.f;
    #pragma unroll 8
    for (int d = 0; d < 256; d++)
        acc += xs[d] * wsel[(size_t)(d0 + d) * D_MODEL + col];
    atomicAdd(&osel[b * D_MODEL + col], acc);
}

__global__ __launch_bounds__(256) void decode_attn_kernel()
{
    const int n = blockIdx.x;
    const int b = blockIdx.y;
    const int tid = threadIdx.x;
    const int lane = tid & 31;
    const int warp = tid >> 5;

    __shared__ float qs[HDIM];
    __shared__ float sc[SEQ + 1];
    __shared__ float red[256];

    if (tid < HDIM) qs[tid] = g_q1[b * D_MODEL + n * HDIM + tid];
    __syncthreads();

    const float scale = QSCALE;
    const float4 qv = *reinterpret_cast<const float4*>(&qs[lane * 4]);

    for (int t = warp; t < SEQ + 1; t += 8) {
        float s;
        if (t < SEQ) {
            const size_t base = (size_t)(b * SEQ + t) * 2048 + n * HDIM + lane * 4;
            uint2 kh = *reinterpret_cast<const uint2*>(&g_Kh[base]);
            uint2 kl = *reinterpret_cast<const uint2*>(&g_Kl[base]);
            float2 h0 = __half22float2(*reinterpret_cast<__half2*>(&kh.x));
            float2 h1 = __half22float2(*reinterpret_cast<__half2*>(&kh.y));
            float2 l0 = __half22float2(*reinterpret_cast<__half2*>(&kl.x));
            float2 l1 = __half22float2(*reinterpret_cast<__half2*>(&kl.y));
            s = qv.x * (h0.x + l0.x) + qv.y * (h0.y + l0.y)
              + qv.z * (h1.x + l1.x) + qv.w * (h1.y + l1.y);
        } else {
            const float* kr = g_k1 + b * D_MODEL + n * HDIM;
            float4 kv = *reinterpret_cast<const float4*>(&kr[lane * 4]);
            s = qv.x * kv.x + qv.y * kv.y + qv.z * kv.z + qv.w * kv.w;
        }
        #pragma unroll
        for (int o = 16; o > 0; o >>= 1) s += __shfl_xor_sync(0xffffffffu, s, o);
        if (lane == 0) sc[t] = s * scale;
    }
    __syncthreads();

    float mx = -INFINITY;
    for (int t = tid; t < SEQ + 1; t += 256) mx = fmaxf(mx, sc[t]);
    red[tid] = mx;
    __syncthreads();
    for (int s = 128; s > 0; s >>= 1) {
        if (tid < s) red[tid] = fmaxf(red[tid], red[tid + s]);
        __syncthreads();
    }
    mx = red[0];
    __syncthreads();

    float sum = 0.f;
    for (int t = tid; t < SEQ + 1; t += 256) {
        float p = __expf(sc[t] - mx);
        sc[t] = p;
        sum += p;
    }
    red[tid] = sum;
    __syncthreads();
    for (int s = 128; s > 0; s >>= 1) {
        if (tid < s) red[tid] += red[tid + s];
        __syncthreads();
    }
    const float inv = 1.f / red[0];
    __syncthreads();

    const int h = tid & 127;
    const int hf = tid >> 7;
    const __half* vth = &g_Vth[(size_t)(n * HDIM + h) * MROWS + b * SEQ + hf * 1024];
    const __half* vtl = &g_Vtl[(size_t)(n * HDIM + h) * MROWS + b * SEQ + hf * 1024];
    const float* scp = &sc[hf * 1024];
    float acc = 0.f;
    for (int t = 0; t < 1024; t += 8) {
        uint4 vh = *reinterpret_cast<const uint4*>(&vth[t]);
        uint4 vl = *reinterpret_cast<const uint4*>(&vtl[t]);
        const __half2* ph = reinterpret_cast<const __half2*>(&vh);
        const __half2* pl = reinterpret_cast<const __half2*>(&vl);
        #pragma unroll
        for (int j = 0; j < 4; j++) {
            float2 fh = __half22float2(ph[j]);
            float2 fl = __half22float2(pl[j]);
            acc += scp[t + 2 * j] * (fh.x + fl.x) + scp[t + 2 * j + 1] * (fh.y + fl.y);
        }
    }
    if (hf == 0) acc += sc[SEQ] * g_v1[b * D_MODEL + n * HDIM + h];
    red[tid] = acc;
    __syncthreads();
    if (tid < 128)
        g_a1[b * D_MODEL + n * HDIM + tid] = (red[tid] + red[tid + 128]) * inv;
}

__global__ __launch_bounds__(256) void decode_out_kernel(
    const float* __restrict__ wo, float* __restrict__ out)
{
    const int gw = (blockIdx.x * 256 + threadIdx.x) >> 5;
    const int lane = threadIdx.x & 31;
    if (gw >= BATCH * D_MODEL) return;
    const int b = gw >> 11;
    const int d = gw & (D_MODEL - 1);

    const float* a = g_a1 + b * D_MODEL;
    const float* w = wo + (size_t)d * D_MODEL;
    float acc = 0.f;
    for (int k = lane * 4; k < D_MODEL; k += 128) {
        float4 av = *reinterpret_cast<const float4*>(a + k);
        float4 wv = *reinterpret_cast<const float4*>(w + k);
        acc += av.x * wv.x + av.y * wv.y + av.z * wv.z + av.w * wv.w;
    }
    #pragma unroll
    for (int o = 16; o > 0; o >>= 1) acc += __shfl_down_sync(0xffffffff, acc, o);
    if (lane == 0) out[PREFILL_ELEMS + b * D_MODEL + d] = acc;
}

// ---------------------------------------------------------------------------
extern "C" void kernel_launch(void* const* d_in, const int* in_sizes, int n_in,
                              void* d_out, int out_size)
{
    const float* x     = (const float*)d_in[0];
    const float* x_new = (const float*)d_in[1];
    const float* wq    = (const float*)d_in[2];
    const float* wk    = (const float*)d_in[3];
    const float* wv    = (const float*)d_in[4];
    const float* wo    = (const float*)d_in[5];
    float* out = (float*)d_out;

    __half *pxh, *pAh, *pwqt, *pwkt, *pwvt, *pwoh;
    cudaGetSymbolAddress((void**)&pxh,  g_xh);
    cudaGetSymbolAddress((void**)&pAh,  g_Ah);
    cudaGetSymbolAddress((void**)&pwqt, g_wqt);
    cudaGetSymbolAddress((void**)&pwkt, g_wkt);
    cudaGetSymbolAddress((void**)&pwvt, g_wvt);
    cudaGetSymbolAddress((void**)&pwoh, g_woh);

    // second stream + events: created once on the (uncaptured) correctness call
    static cudaStream_t s2 = nullptr;
    static cudaEvent_t evFork = nullptr, evJoin = nullptr;
    if (!s2) {
        cudaStreamCreateWithFlags(&s2, cudaStreamNonBlocking);
        cudaEventCreateWithFlags(&evFork, cudaEventDisableTiming);
        cudaEventCreateWithFlags(&evJoin, cudaEventDisableTiming);
        cudaFuncSetAttribute(flash_hmma_kernel,
                             cudaFuncAttributeMaxDynamicSharedMemorySize, FLASH_SMEM_BYTES);
        cudaFuncSetAttribute(hgemm_kernel<0>,
                             cudaFuncAttributeMaxDynamicSharedMemorySize, GEMM_SMEM_BYTES);
        cudaFuncSetAttribute(hgemm_kernel<1>,
                             cudaFuncAttributeMaxDynamicSharedMemorySize, GEMM_SMEM_BYTES);
    }

    // 0. one-time conversions (main stream)
    convert_x_kernel<<<PREFILL_ELEMS / 4 / 256, 256>>>(x);
    convert_wo_kernel<<<(D_MODEL * D_MODEL) / 4 / 256, 256>>>(wo);
    dim3 wtg(64, 64, 3);
    convert_wt_kernel<<<wtg, 256>>>(wq, wk, wv);

    // 1. Fused Q/K/V projections
    hgemm_kernel<0><<<NPERSIST, 256, GEMM_SMEM_BYTES>>>(pxh, pwqt, pwkt, pwvt, nullptr, 1536);

    // fork: decode chain on s2 (needs only QKV outputs + raw inputs)
    cudaEventRecord(evFork, 0);
    cudaStreamWaitEvent(s2, evFork, 0);
    decode_init_kernel<<<(BATCH * D_MODEL + 255) / 256, 256, 0, s2>>>();
    dim3 dpgrid(D_MODEL / 256, BATCH * 3, 8);
    decode_proj_kernel<<<dpgrid, 256, 0, s2>>>(x_new, wq, wk, wv);
    dim3 dagrid(NHEADS, BATCH);
    decode_attn_kernel<<<dagrid, 256, 0, s2>>>();
    decode_out_kernel<<<512, 256, 0, s2>>>(wo, out);
    cudaEventRecord(evJoin, s2);

    // main stream: flash + out-projection
    dim3 fgrid(SEQ / 64, NHEADS, BATCH);
    flash_hmma_kernel<<<fgrid, 256, FLASH_SMEM_BYTES>>>();
    hgemm_kernel<1><<<NPERSIST, 256, GEMM_SMEM_BYTES>>>(pAh, pwoh, pwoh, pwoh, out, 512);

    // join
    cudaStreamWaitEvent(0, evJoin, 0);
}